// round 12
// baseline (speedup 1.0000x reference)
#include <cuda_runtime.h>
#include <cuda_fp16.h>
#include <cstdint>

#define MAXN 100000
#define MAXE 1600000
#define DIN  64

// ---------------- scratch (no cudaMalloc allowed) ----------------
__device__ __half g_XEh[(size_t)MAXN * 64];  // sum of e * X[src] per dst (fp16)
__device__ __half g_X1h[(size_t)MAXN * 64];  // sum of X[src] per dst (fp16)
__device__ __half g_Xh[(size_t)MAXN * 64];   // fp16 copy of input x
__device__ __half g_HAh[(size_t)MAXN * 64];  // relu(layer1 out), fp16
__device__ __half g_HBh[(size_t)MAXN * 64];  // relu(layer2 out), fp16
__device__ int    g_counts[MAXN];
__device__ int    g_off[MAXN + 1];
__device__ int    g_cursor[MAXN];
__device__ int    g_bsum[64];
__device__ int    g_boff[64];
__device__ int2   g_meta[MAXE];              // {src, bits(e)} grouped by dst

// pre-split tf32 weights: [mat 0..8][hi/lo][n*68+k]
#define APAD 68
#define WSEG_FLOATS (64 * APAD)              /* 4352 */
__device__ float g_Wsp[9 * 2 * WSEG_FLOATS];

// =================================================================
// CSR build (unchanged from R11 winner)
// =================================================================
__global__ void zero_kernel(int* __restrict__ counts, int N)
{
    int i = blockIdx.x * blockDim.x + threadIdx.x;
    if (i < N) counts[i] = 0;
}

__global__ void hist_kernel(const int* __restrict__ ei, int* __restrict__ counts, int E)
{
    int i = blockIdx.x * blockDim.x + threadIdx.x;
    int base = i * 4;
    if (base >= E) return;
    if (((E & 3) == 0) && (base + 4 <= E)) {
        int4 d = *reinterpret_cast<const int4*>(ei + E + base);
        atomicAdd(&counts[d.x], 1);
        atomicAdd(&counts[d.y], 1);
        atomicAdd(&counts[d.z], 1);
        atomicAdd(&counts[d.w], 1);
    } else {
        int hi = min(base + 4, E);
        for (int e = base; e < hi; e++) atomicAdd(&counts[__ldg(ei + E + e)], 1);
    }
}

__global__ __launch_bounds__(256) void scanA_kernel(const int* __restrict__ counts,
                                                    int* __restrict__ bsum, int N)
{
    __shared__ int red[256];
    int tid = threadIdx.x;
    int base = blockIdx.x * 2048 + tid * 8;
    int s = 0;
    if (base < N) {
        int4 a = *reinterpret_cast<const int4*>(counts + base);
        int4 b = *reinterpret_cast<const int4*>(counts + base + 4);
        s = a.x + a.y + a.z + a.w + b.x + b.y + b.z + b.w;
    }
    red[tid] = s;
    __syncthreads();
    #pragma unroll
    for (int d = 128; d > 0; d >>= 1) {
        if (tid < d) red[tid] += red[tid + d];
        __syncthreads();
    }
    if (tid == 0) bsum[blockIdx.x] = red[0];
}

__global__ __launch_bounds__(64) void scanB_kernel(const int* __restrict__ bsum,
                                                   int* __restrict__ boff,
                                                   int* __restrict__ off, int B, int N)
{
    __shared__ int sh[64];
    int tid = threadIdx.x;
    int v = (tid < B) ? bsum[tid] : 0;
    sh[tid] = v;
    __syncthreads();
    #pragma unroll
    for (int d = 1; d < 64; d <<= 1) {
        int t = (tid >= d) ? sh[tid - d] : 0;
        __syncthreads();
        sh[tid] += t;
        __syncthreads();
    }
    boff[tid] = sh[tid] - v;
    if (tid == 63) off[N] = sh[63];
}

__global__ __launch_bounds__(256) void scanC_kernel(const int* __restrict__ counts,
                                                    const int* __restrict__ boff,
                                                    int* __restrict__ off,
                                                    int* __restrict__ cursor, int N)
{
    __shared__ int wsum[8], woff[8];
    int tid = threadIdx.x;
    int lane = tid & 31;
    int warp = tid >> 5;
    int base = blockIdx.x * 2048 + tid * 8;

    int4 a = make_int4(0, 0, 0, 0), b = make_int4(0, 0, 0, 0);
    if (base < N) {
        a = *reinterpret_cast<const int4*>(counts + base);
        b = *reinterpret_cast<const int4*>(counts + base + 4);
    }
    int s = a.x + a.y + a.z + a.w + b.x + b.y + b.z + b.w;

    int incl = s;
    #pragma unroll
    for (int d = 1; d < 32; d <<= 1) {
        int t = __shfl_up_sync(0xFFFFFFFFu, incl, d);
        if (lane >= d) incl += t;
    }
    if (lane == 31) wsum[warp] = incl;
    __syncthreads();
    if (tid == 0) {
        int run = 0;
        #pragma unroll
        for (int j = 0; j < 8; j++) { int t = wsum[j]; woff[j] = run; run += t; }
    }
    __syncthreads();

    int ex = __ldg(boff + blockIdx.x) + woff[warp] + (incl - s);
    if (base < N) {
        int o0 = ex;
        int o1 = o0 + a.x, o2 = o1 + a.y, o3 = o2 + a.z, o4 = o3 + a.w;
        int o5 = o4 + b.x, o6 = o5 + b.y, o7 = o6 + b.z;
        int4 oa = make_int4(o0, o1, o2, o3);
        int4 ob = make_int4(o4, o5, o6, o7);
        *reinterpret_cast<int4*>(off + base)        = oa;
        *reinterpret_cast<int4*>(off + base + 4)    = ob;
        *reinterpret_cast<int4*>(cursor + base)     = oa;
        *reinterpret_cast<int4*>(cursor + base + 4) = ob;
    }
}

__global__ void scatter_kernel(const int* __restrict__ ei, const float* __restrict__ ea,
                               int* __restrict__ cursor, int2* __restrict__ meta, int E)
{
    int i = blockIdx.x * blockDim.x + threadIdx.x;
    int base = i * 4;
    if (base >= E) return;
    if (((E & 3) == 0) && (base + 4 <= E)) {
        int4 s4 = *reinterpret_cast<const int4*>(ei + base);
        int4 d4 = *reinterpret_cast<const int4*>(ei + E + base);
        float4 e4 = *reinterpret_cast<const float4*>(ea + base);
        int p0 = atomicAdd(&cursor[d4.x], 1);
        int p1 = atomicAdd(&cursor[d4.y], 1);
        int p2 = atomicAdd(&cursor[d4.z], 1);
        int p3 = atomicAdd(&cursor[d4.w], 1);
        meta[p0] = make_int2(s4.x, __float_as_int(e4.x));
        meta[p1] = make_int2(s4.y, __float_as_int(e4.y));
        meta[p2] = make_int2(s4.z, __float_as_int(e4.z));
        meta[p3] = make_int2(s4.w, __float_as_int(e4.w));
    } else {
        int hi = min(base + 4, E);
        for (int e = base; e < hi; e++) {
            int s = __ldg(ei + e);
            int d = __ldg(ei + E + e);
            int pos = atomicAdd(&cursor[d], 1);
            meta[pos] = make_int2(s, __float_as_int(__ldg(ea + e)));
        }
    }
}

// =================================================================
// tf32 split + weight pre-split (unchanged)
// =================================================================
__device__ __forceinline__ void split_tf32(float v, uint32_t& hi, uint32_t& lo)
{
    asm("cvt.rna.tf32.f32 %0, %1;" : "=r"(hi) : "f"(v));
    float r = v - __uint_as_float(hi);
    asm("cvt.rna.tf32.f32 %0, %1;" : "=r"(lo) : "f"(r));
}

__global__ __launch_bounds__(256) void presplit_kernel(
    const float* __restrict__ m0, const float* __restrict__ m1, const float* __restrict__ m2,
    const float* __restrict__ m3, const float* __restrict__ m4, const float* __restrict__ m5,
    const float* __restrict__ m6, const float* __restrict__ m7, const float* __restrict__ m8,
    float* __restrict__ out)
{
    int idx = blockIdx.x * blockDim.x + threadIdx.x;
    if (idx >= 9 * 4096) return;
    int mat = idx >> 12;
    int j = idx & 4095;
    int k = j >> 6;
    int n = j & 63;

    const float* src;
    switch (mat) {
        case 0: src = m0; break; case 1: src = m1; break; case 2: src = m2; break;
        case 3: src = m3; break; case 4: src = m4; break; case 5: src = m5; break;
        case 6: src = m6; break; case 7: src = m7; break; default: src = m8; break;
    }
    uint32_t hi, lo;
    split_tf32(__ldg(src + j), hi, lo);
    float* dst = out + (size_t)mat * 2 * WSEG_FLOATS;
    dst[n * APAD + k]               = __uint_as_float(hi);
    dst[WSEG_FLOATS + n * APAD + k] = __uint_as_float(lo);
}

// =================================================================
// x -> fp16 conversion (one-time)
// =================================================================
__global__ __launch_bounds__(256) void cvt_half_kernel(const float* __restrict__ X,
                                                       __half* __restrict__ Xh, int total)
{
    int i = blockIdx.x * blockDim.x + threadIdx.x;
    int base = i * 8;
    if (base >= total) return;
    float4 a = *reinterpret_cast<const float4*>(X + base);
    float4 b = *reinterpret_cast<const float4*>(X + base + 4);
    __half2 h[4];
    h[0] = __float22half2_rn(make_float2(a.x, a.y));
    h[1] = __float22half2_rn(make_float2(a.z, a.w));
    h[2] = __float22half2_rn(make_float2(b.x, b.y));
    h[3] = __float22half2_rn(make_float2(b.z, b.w));
    *reinterpret_cast<uint4*>(Xh + base) = *reinterpret_cast<uint4*>(h);
}

// =================================================================
// fp16-gather aggregation, shfl-batched meta + unroll-4 gathers.
// warp per node; lane owns 2 channels (half2 = 4B per edge).
// =================================================================
__global__ __launch_bounds__(256) void aggx_h_kernel(const int* __restrict__ off,
                                                     const int2* __restrict__ meta,
                                                     const __half* __restrict__ Xh,
                                                     __half* __restrict__ XEh,
                                                     __half* __restrict__ X1h, int N)
{
    int w = (blockIdx.x * blockDim.x + threadIdx.x) >> 5;
    int lane = threadIdx.x & 31;
    if (w >= N) return;

    int beg = __ldg(off + w);
    int end = __ldg(off + w + 1);

    float2 aE = make_float2(0.f, 0.f);
    float2 a1 = make_float2(0.f, 0.f);

    const __half2* X2 = reinterpret_cast<const __half2*>(Xh);

    for (int base = beg; base < end; base += 32) {
        int cnt = end - base;
        if (cnt > 32) cnt = 32;
        // one coalesced meta load covers up to 32 edges
        int2 m = __ldg(meta + base + (lane < cnt ? lane : cnt - 1));

        int j = 0;
        for (; j + 4 <= cnt; j += 4) {
            int s0 = __shfl_sync(0xFFFFFFFFu, m.x, j);
            int s1 = __shfl_sync(0xFFFFFFFFu, m.x, j + 1);
            int s2 = __shfl_sync(0xFFFFFFFFu, m.x, j + 2);
            int s3 = __shfl_sync(0xFFFFFFFFu, m.x, j + 3);
            float e0 = __int_as_float(__shfl_sync(0xFFFFFFFFu, m.y, j));
            float e1 = __int_as_float(__shfl_sync(0xFFFFFFFFu, m.y, j + 1));
            float e2 = __int_as_float(__shfl_sync(0xFFFFFFFFu, m.y, j + 2));
            float e3 = __int_as_float(__shfl_sync(0xFFFFFFFFu, m.y, j + 3));
            // 4 independent gathers in flight
            float2 v0 = __half22float2(X2[(size_t)s0 * 32 + lane]);
            float2 v1 = __half22float2(X2[(size_t)s1 * 32 + lane]);
            float2 v2 = __half22float2(X2[(size_t)s2 * 32 + lane]);
            float2 v3 = __half22float2(X2[(size_t)s3 * 32 + lane]);
            aE.x = fmaf(e0, v0.x, aE.x); aE.y = fmaf(e0, v0.y, aE.y);
            aE.x = fmaf(e1, v1.x, aE.x); aE.y = fmaf(e1, v1.y, aE.y);
            aE.x = fmaf(e2, v2.x, aE.x); aE.y = fmaf(e2, v2.y, aE.y);
            aE.x = fmaf(e3, v3.x, aE.x); aE.y = fmaf(e3, v3.y, aE.y);
            a1.x += (v0.x + v1.x) + (v2.x + v3.x);
            a1.y += (v0.y + v1.y) + (v2.y + v3.y);
        }
        for (; j < cnt; j++) {
            int s0 = __shfl_sync(0xFFFFFFFFu, m.x, j);
            float e0 = __int_as_float(__shfl_sync(0xFFFFFFFFu, m.y, j));
            float2 v0 = __half22float2(X2[(size_t)s0 * 32 + lane]);
            aE.x = fmaf(e0, v0.x, aE.x); aE.y = fmaf(e0, v0.y, aE.y);
            a1.x += v0.x;                a1.y += v0.y;
        }
    }

    reinterpret_cast<__half2*>(XEh)[(size_t)w * 32 + lane] = __float22half2_rn(aE);
    reinterpret_cast<__half2*>(X1h)[(size_t)w * 32 + lane] = __float22half2_rn(a1);
}

// =================================================================
// TF32 tensor-core GEMM (unchanged from R11 winner)
// =================================================================
#define SA_FLOATS (128 * APAD)     /* 8704 */
#define TC_SMEM_FLOATS (SA_FLOATS + 2 * WSEG_FLOATS)
#define TC_SMEM_BYTES  (TC_SMEM_FLOATS * 4)   /* 69632 B */

__device__ __forceinline__ void mma_tf32(float* c, const uint32_t* a, const uint32_t* b)
{
    asm("mma.sync.aligned.m16n8k8.row.col.f32.tf32.tf32.f32 "
        "{%0,%1,%2,%3}, {%4,%5,%6,%7}, {%8,%9}, {%0,%1,%2,%3};"
        : "+f"(c[0]), "+f"(c[1]), "+f"(c[2]), "+f"(c[3])
        : "r"(a[0]), "r"(a[1]), "r"(a[2]), "r"(a[3]), "r"(b[0]), "r"(b[1]));
}

__global__ __launch_bounds__(256, 3) void gemm192_tc(const __half* __restrict__ XEh,
                                                     const __half* __restrict__ X1h,
                                                     const __half* __restrict__ Xh,
                                                     const float* __restrict__ Wsp,
                                                     const float* __restrict__ bias,
                                                     __half* __restrict__ Hh, int N)
{
    extern __shared__ float sm[];
    float* sA   = sm;
    float* sWhi = sm + SA_FLOATS;
    float* sWlo = sWhi + WSEG_FLOATS;

    const int tid  = threadIdx.x;
    const int lane = tid & 31;
    const int wid  = tid >> 5;
    const int grp  = lane >> 2;
    const int qid  = lane & 3;
    const int wm   = wid & 3;
    const int wn   = wid >> 2;
    const int row0 = blockIdx.x * 128;

    float c[2][4][4];
    #pragma unroll
    for (int mt = 0; mt < 2; mt++)
        #pragma unroll
        for (int nt = 0; nt < 4; nt++)
            #pragma unroll
            for (int j = 0; j < 4; j++) c[mt][nt][j] = 0.f;

    #pragma unroll
    for (int seg = 0; seg < 3; seg++) {
        const __half* A = (seg == 0) ? XEh : (seg == 1) ? X1h : Xh;
        const float* Wseg = Wsp + (size_t)seg * 2 * WSEG_FLOATS;

        if (seg > 0) __syncthreads();

        #pragma unroll
        for (int i = tid; i < 2048; i += 256) {
            int r  = i >> 4;
            int k4 = (i & 15) * 4;
            int row = row0 + r;
            float4 v = make_float4(0.f, 0.f, 0.f, 0.f);
            if (row < N) {
                uint2 hv = *reinterpret_cast<const uint2*>(A + (size_t)row * 64 + k4);
                float2 lo2 = __half22float2(*reinterpret_cast<__half2*>(&hv.x));
                float2 hi2 = __half22float2(*reinterpret_cast<__half2*>(&hv.y));
                v = make_float4(lo2.x, lo2.y, hi2.x, hi2.y);
            }
            *reinterpret_cast<float4*>(&sA[r * APAD + k4]) = v;
        }
        #pragma unroll
        for (int i = tid; i < 2176; i += 256) {
            float4 v = __ldg(reinterpret_cast<const float4*>(Wseg) + i);
            *reinterpret_cast<float4*>(&sWhi[i * 4]) = v;
        }
        __syncthreads();

        #pragma unroll
        for (int kst = 0; kst < 8; kst++) {
            const int k0 = kst * 8;

            uint32_t a[2][4];
            #pragma unroll
            for (int mt = 0; mt < 2; mt++) {
                int r0 = (wm * 32 + mt * 16 + grp) * APAD + k0 + qid;
                int r1 = r0 + 8 * APAD;
                a[mt][0] = __float_as_uint(sA[r0]);
                a[mt][1] = __float_as_uint(sA[r1]);
                a[mt][2] = __float_as_uint(sA[r0 + 4]);
                a[mt][3] = __float_as_uint(sA[r1 + 4]);
            }
            uint32_t bhi[4][2], blo[4][2];
            #pragma unroll
            for (int nt = 0; nt < 4; nt++) {
                int b0 = (wn * 32 + nt * 8 + grp) * APAD + k0 + qid;
                bhi[nt][0] = __float_as_uint(sWhi[b0]);
                bhi[nt][1] = __float_as_uint(sWhi[b0 + 4]);
                blo[nt][0] = __float_as_uint(sWlo[b0]);
                blo[nt][1] = __float_as_uint(sWlo[b0 + 4]);
            }

            #pragma unroll
            for (int mt = 0; mt < 2; mt++) {
                #pragma unroll
                for (int nt = 0; nt < 4; nt++) {
                    mma_tf32(c[mt][nt], a[mt], bhi[nt]);
                    mma_tf32(c[mt][nt], a[mt], blo[nt]);
                }
            }
        }
    }

    #pragma unroll
    for (int mt = 0; mt < 2; mt++) {
        int rbase = row0 + wm * 32 + mt * 16 + grp;
        #pragma unroll
        for (int nt = 0; nt < 4; nt++) {
            int col = wn * 32 + nt * 8 + 2 * qid;
            float2 b2 = __ldg(reinterpret_cast<const float2*>(bias + col));
            if (rbase < N) {
                float2 v = make_float2(fmaxf(c[mt][nt][0] + b2.x, 0.f),
                                       fmaxf(c[mt][nt][1] + b2.y, 0.f));
                *reinterpret_cast<__half2*>(Hh + (size_t)rbase * 64 + col) = __float22half2_rn(v);
            }
            if (rbase + 8 < N) {
                float2 v = make_float2(fmaxf(c[mt][nt][2] + b2.x, 0.f),
                                       fmaxf(c[mt][nt][3] + b2.y, 0.f));
                *reinterpret_cast<__half2*>(Hh + (size_t)(rbase + 8) * 64 + col) = __float22half2_rn(v);
            }
        }
    }
}

// =================================================================
// Layer 3 fully fused, shfl-batched gather + projection + log_softmax
// =================================================================
__global__ __launch_bounds__(256) void agg3_ls(const int* __restrict__ off,
                                               const int2* __restrict__ meta,
                                               const __half* __restrict__ HBh,
                                               const float* __restrict__ Wm,
                                               const float* __restrict__ Bm,
                                               const float* __restrict__ Wr,
                                               const float* __restrict__ b,
                                               float* __restrict__ OUT, int N)
{
    __shared__ float sw[768];
    int tid = threadIdx.x;
    if (tid < 256) { sw[tid] = Wm[tid]; sw[256 + tid] = Bm[tid]; sw[512 + tid] = Wr[tid]; }
    __syncthreads();

    int w = (blockIdx.x * blockDim.x + tid) >> 5;
    int lane = tid & 31;
    if (w >= N) return;

    int beg = __ldg(off + w);
    int end = __ldg(off + w + 1);

    float2 aE = make_float2(0.f, 0.f);
    float2 a1 = make_float2(0.f, 0.f);

    const __half2* X2 = reinterpret_cast<const __half2*>(HBh);

    for (int base = beg; base < end; base += 32) {
        int cnt = end - base;
        if (cnt > 32) cnt = 32;
        int2 m = __ldg(meta + base + (lane < cnt ? lane : cnt - 1));

        int j = 0;
        for (; j + 4 <= cnt; j += 4) {
            int s0 = __shfl_sync(0xFFFFFFFFu, m.x, j);
            int s1 = __shfl_sync(0xFFFFFFFFu, m.x, j + 1);
            int s2 = __shfl_sync(0xFFFFFFFFu, m.x, j + 2);
            int s3 = __shfl_sync(0xFFFFFFFFu, m.x, j + 3);
            float e0 = __int_as_float(__shfl_sync(0xFFFFFFFFu, m.y, j));
            float e1 = __int_as_float(__shfl_sync(0xFFFFFFFFu, m.y, j + 1));
            float e2 = __int_as_float(__shfl_sync(0xFFFFFFFFu, m.y, j + 2));
            float e3 = __int_as_float(__shfl_sync(0xFFFFFFFFu, m.y, j + 3));
            float2 v0 = __half22float2(X2[(size_t)s0 * 32 + lane]);
            float2 v1 = __half22float2(X2[(size_t)s1 * 32 + lane]);
            float2 v2 = __half22float2(X2[(size_t)s2 * 32 + lane]);
            float2 v3 = __half22float2(X2[(size_t)s3 * 32 + lane]);
            aE.x = fmaf(e0, v0.x, aE.x); aE.y = fmaf(e0, v0.y, aE.y);
            aE.x = fmaf(e1, v1.x, aE.x); aE.y = fmaf(e1, v1.y, aE.y);
            aE.x = fmaf(e2, v2.x, aE.x); aE.y = fmaf(e2, v2.y, aE.y);
            aE.x = fmaf(e3, v3.x, aE.x); aE.y = fmaf(e3, v3.y, aE.y);
            a1.x += (v0.x + v1.x) + (v2.x + v3.x);
            a1.y += (v0.y + v1.y) + (v2.y + v3.y);
        }
        for (; j < cnt; j++) {
            int s0 = __shfl_sync(0xFFFFFFFFu, m.x, j);
            float e0 = __int_as_float(__shfl_sync(0xFFFFFFFFu, m.y, j));
            float2 v0 = __half22float2(X2[(size_t)s0 * 32 + lane]);
            aE.x = fmaf(e0, v0.x, aE.x); aE.y = fmaf(e0, v0.y, aE.y);
            a1.x += v0.x;                a1.y += v0.y;
        }
    }

    float2 hb = __half22float2(X2[(size_t)w * 32 + lane]);

    const int k0 = lane * 2 * 4;
    float p[4];
    #pragma unroll
    for (int c = 0; c < 4; c++) {
        float v = aE.x * sw[k0 + c] + aE.y * sw[k0 + 4 + c];
        v = fmaf(a1.x, sw[256 + k0 + c], v);
        v = fmaf(a1.y, sw[256 + k0 + 4 + c], v);
        v = fmaf(hb.x, sw[512 + k0 + c], v);
        v = fmaf(hb.y, sw[512 + k0 + 4 + c], v);
        p[c] = v;
    }
    #pragma unroll
    for (int d = 16; d > 0; d >>= 1) {
        p[0] += __shfl_xor_sync(0xFFFFFFFFu, p[0], d);
        p[1] += __shfl_xor_sync(0xFFFFFFFFu, p[1], d);
        p[2] += __shfl_xor_sync(0xFFFFFFFFu, p[2], d);
        p[3] += __shfl_xor_sync(0xFFFFFFFFu, p[3], d);
    }

    if (lane == 0) {
        #pragma unroll
        for (int c = 0; c < 4; c++) p[c] += __ldg(b + c);
        float m = fmaxf(fmaxf(p[0], p[1]), fmaxf(p[2], p[3]));
        float s = __expf(p[0] - m) + __expf(p[1] - m) +
                  __expf(p[2] - m) + __expf(p[3] - m);
        float lse = m + __logf(s);
        float4 o;
        o.x = p[0] - lse; o.y = p[1] - lse; o.z = p[2] - lse; o.w = p[3] - lse;
        *reinterpret_cast<float4*>(OUT + (size_t)w * 4) = o;
    }
}

// =================================================================
extern "C" void kernel_launch(void* const* d_in, const int* in_sizes, int n_in,
                              void* d_out, int out_size)
{
    const float* x   = (const float*)d_in[0];
    const int*   ei  = (const int*)  d_in[1];
    const float* ea  = (const float*)d_in[2];
    const float* We1 = (const float*)d_in[3];
    const float* be1 = (const float*)d_in[4];
    const float* Wr1 = (const float*)d_in[5];
    const float* b1  = (const float*)d_in[6];
    const float* We2 = (const float*)d_in[7];
    const float* be2 = (const float*)d_in[8];
    const float* Wr2 = (const float*)d_in[9];
    const float* b2  = (const float*)d_in[10];
    const float* We3 = (const float*)d_in[11];
    const float* be3 = (const float*)d_in[12];
    const float* Wr3 = (const float*)d_in[13];
    const float* b3  = (const float*)d_in[14];

    const int N = in_sizes[0] / DIN;
    const int E = in_sizes[2];

    float *Wsp, *OUT = (float*)d_out;
    __half *XEh, *X1h, *Xh, *HAh, *HBh;
    int *counts, *off, *cursor, *bsum, *boff;
    int2 *meta;
    cudaGetSymbolAddress((void**)&XEh, g_XEh);
    cudaGetSymbolAddress((void**)&X1h, g_X1h);
    cudaGetSymbolAddress((void**)&Xh, g_Xh);
    cudaGetSymbolAddress((void**)&HAh, g_HAh);
    cudaGetSymbolAddress((void**)&HBh, g_HBh);
    cudaGetSymbolAddress((void**)&Wsp, g_Wsp);
    cudaGetSymbolAddress((void**)&counts, g_counts);
    cudaGetSymbolAddress((void**)&off, g_off);
    cudaGetSymbolAddress((void**)&cursor, g_cursor);
    cudaGetSymbolAddress((void**)&bsum, g_bsum);
    cudaGetSymbolAddress((void**)&boff, g_boff);
    cudaGetSymbolAddress((void**)&meta, g_meta);

    cudaFuncSetAttribute(gemm192_tc, cudaFuncAttributeMaxDynamicSharedMemorySize, TC_SMEM_BYTES);

    const int edge4Grid = (E / 4 + 256) / 256;
    const int rowGrid   = (N + 255) / 256;
    const int aggGrid   = (N * 32 + 255) / 256;
    const int tcGrid    = (N + 127) / 128;
    const int scanGrid  = (N + 2047) / 2048;
    const int cvtGrid   = (N * 64 / 8 + 255) / 256;

    // ---- CSR build + weight pre-split + x->fp16 ----
    zero_kernel<<<rowGrid, 256>>>(counts, N);
    hist_kernel<<<edge4Grid, 256>>>(ei, counts, E);
    scanA_kernel<<<scanGrid, 256>>>(counts, bsum, N);
    scanB_kernel<<<1, 64>>>(bsum, boff, off, scanGrid, N);
    scanC_kernel<<<scanGrid, 256>>>(counts, boff, off, cursor, N);
    scatter_kernel<<<edge4Grid, 256>>>(ei, ea, cursor, meta, E);
    presplit_kernel<<<144, 256>>>(We1, be1, Wr1, We2, be2, Wr2, We3, be3, Wr3, Wsp);
    cvt_half_kernel<<<cvtGrid, 256>>>(x, Xh, N * 64);

    // ---- layer 1 ----
    aggx_h_kernel<<<aggGrid, 256>>>(off, meta, Xh, XEh, X1h, N);
    gemm192_tc<<<tcGrid, 256, TC_SMEM_BYTES>>>(XEh, X1h, Xh, Wsp, b1, HAh, N);

    // ---- layer 2 ----
    aggx_h_kernel<<<aggGrid, 256>>>(off, meta, HAh, XEh, X1h, N);
    gemm192_tc<<<tcGrid, 256, TC_SMEM_BYTES>>>(XEh, X1h, HAh,
                                               Wsp + (size_t)3 * 2 * WSEG_FLOATS, b2, HBh, N);

    // ---- layer 3 (fully fused) ----
    agg3_ls<<<aggGrid, 256>>>(off, meta, HBh, We3, be3, Wr3, b3, OUT, N);
}

// round 13
// speedup vs baseline: 1.0012x; 1.0012x over previous
#include <cuda_runtime.h>
#include <cuda_fp16.h>
#include <cstdint>

#define MAXN 100000
#define MAXE 1600000
#define DIN  64

// ---------------- scratch (no cudaMalloc allowed) ----------------
__device__ __half g_XEh[(size_t)MAXN * 64];  // sum of e * X[src] per dst (fp16)
__device__ __half g_X1h[(size_t)MAXN * 64];  // sum of X[src] per dst (fp16)
__device__ __half g_Xh[(size_t)MAXN * 64];   // fp16 copy of input x
__device__ __half g_HAh[(size_t)MAXN * 64];  // relu(layer1 out), fp16
__device__ __half g_HBh[(size_t)MAXN * 64];  // relu(layer2 out), fp16
__device__ int    g_counts[MAXN];
__device__ int    g_off[MAXN + 1];
__device__ int    g_cursor[MAXN];
__device__ int    g_bsum[64];
__device__ int    g_boff[64];
__device__ int2   g_meta[MAXE];              // {src, bits(e)} grouped by dst

// pre-split tf32 weights: [mat 0..8][hi/lo][n*68+k]
#define APAD 68
#define WSEG_FLOATS (64 * APAD)              /* 4352 */
__device__ float g_Wsp[9 * 2 * WSEG_FLOATS];

// =================================================================
// CSR build (unchanged from R11 winner)
// =================================================================
__global__ void zero_kernel(int* __restrict__ counts, int N)
{
    int i = blockIdx.x * blockDim.x + threadIdx.x;
    if (i < N) counts[i] = 0;
}

__global__ void hist_kernel(const int* __restrict__ ei, int* __restrict__ counts, int E)
{
    int i = blockIdx.x * blockDim.x + threadIdx.x;
    int base = i * 4;
    if (base >= E) return;
    if (((E & 3) == 0) && (base + 4 <= E)) {
        int4 d = *reinterpret_cast<const int4*>(ei + E + base);
        atomicAdd(&counts[d.x], 1);
        atomicAdd(&counts[d.y], 1);
        atomicAdd(&counts[d.z], 1);
        atomicAdd(&counts[d.w], 1);
    } else {
        int hi = min(base + 4, E);
        for (int e = base; e < hi; e++) atomicAdd(&counts[__ldg(ei + E + e)], 1);
    }
}

__global__ __launch_bounds__(256) void scanA_kernel(const int* __restrict__ counts,
                                                    int* __restrict__ bsum, int N)
{
    __shared__ int red[256];
    int tid = threadIdx.x;
    int base = blockIdx.x * 2048 + tid * 8;
    int s = 0;
    if (base < N) {
        int4 a = *reinterpret_cast<const int4*>(counts + base);
        int4 b = *reinterpret_cast<const int4*>(counts + base + 4);
        s = a.x + a.y + a.z + a.w + b.x + b.y + b.z + b.w;
    }
    red[tid] = s;
    __syncthreads();
    #pragma unroll
    for (int d = 128; d > 0; d >>= 1) {
        if (tid < d) red[tid] += red[tid + d];
        __syncthreads();
    }
    if (tid == 0) bsum[blockIdx.x] = red[0];
}

__global__ __launch_bounds__(64) void scanB_kernel(const int* __restrict__ bsum,
                                                   int* __restrict__ boff,
                                                   int* __restrict__ off, int B, int N)
{
    __shared__ int sh[64];
    int tid = threadIdx.x;
    int v = (tid < B) ? bsum[tid] : 0;
    sh[tid] = v;
    __syncthreads();
    #pragma unroll
    for (int d = 1; d < 64; d <<= 1) {
        int t = (tid >= d) ? sh[tid - d] : 0;
        __syncthreads();
        sh[tid] += t;
        __syncthreads();
    }
    boff[tid] = sh[tid] - v;
    if (tid == 63) off[N] = sh[63];
}

__global__ __launch_bounds__(256) void scanC_kernel(const int* __restrict__ counts,
                                                    const int* __restrict__ boff,
                                                    int* __restrict__ off,
                                                    int* __restrict__ cursor, int N)
{
    __shared__ int wsum[8], woff[8];
    int tid = threadIdx.x;
    int lane = tid & 31;
    int warp = tid >> 5;
    int base = blockIdx.x * 2048 + tid * 8;

    int4 a = make_int4(0, 0, 0, 0), b = make_int4(0, 0, 0, 0);
    if (base < N) {
        a = *reinterpret_cast<const int4*>(counts + base);
        b = *reinterpret_cast<const int4*>(counts + base + 4);
    }
    int s = a.x + a.y + a.z + a.w + b.x + b.y + b.z + b.w;

    int incl = s;
    #pragma unroll
    for (int d = 1; d < 32; d <<= 1) {
        int t = __shfl_up_sync(0xFFFFFFFFu, incl, d);
        if (lane >= d) incl += t;
    }
    if (lane == 31) wsum[warp] = incl;
    __syncthreads();
    if (tid == 0) {
        int run = 0;
        #pragma unroll
        for (int j = 0; j < 8; j++) { int t = wsum[j]; woff[j] = run; run += t; }
    }
    __syncthreads();

    int ex = __ldg(boff + blockIdx.x) + woff[warp] + (incl - s);
    if (base < N) {
        int o0 = ex;
        int o1 = o0 + a.x, o2 = o1 + a.y, o3 = o2 + a.z, o4 = o3 + a.w;
        int o5 = o4 + b.x, o6 = o5 + b.y, o7 = o6 + b.z;
        int4 oa = make_int4(o0, o1, o2, o3);
        int4 ob = make_int4(o4, o5, o6, o7);
        *reinterpret_cast<int4*>(off + base)        = oa;
        *reinterpret_cast<int4*>(off + base + 4)    = ob;
        *reinterpret_cast<int4*>(cursor + base)     = oa;
        *reinterpret_cast<int4*>(cursor + base + 4) = ob;
    }
}

__global__ void scatter_kernel(const int* __restrict__ ei, const float* __restrict__ ea,
                               int* __restrict__ cursor, int2* __restrict__ meta, int E)
{
    int i = blockIdx.x * blockDim.x + threadIdx.x;
    int base = i * 4;
    if (base >= E) return;
    if (((E & 3) == 0) && (base + 4 <= E)) {
        int4 s4 = *reinterpret_cast<const int4*>(ei + base);
        int4 d4 = *reinterpret_cast<const int4*>(ei + E + base);
        float4 e4 = *reinterpret_cast<const float4*>(ea + base);
        int p0 = atomicAdd(&cursor[d4.x], 1);
        int p1 = atomicAdd(&cursor[d4.y], 1);
        int p2 = atomicAdd(&cursor[d4.z], 1);
        int p3 = atomicAdd(&cursor[d4.w], 1);
        meta[p0] = make_int2(s4.x, __float_as_int(e4.x));
        meta[p1] = make_int2(s4.y, __float_as_int(e4.y));
        meta[p2] = make_int2(s4.z, __float_as_int(e4.z));
        meta[p3] = make_int2(s4.w, __float_as_int(e4.w));
    } else {
        int hi = min(base + 4, E);
        for (int e = base; e < hi; e++) {
            int s = __ldg(ei + e);
            int d = __ldg(ei + E + e);
            int pos = atomicAdd(&cursor[d], 1);
            meta[pos] = make_int2(s, __float_as_int(__ldg(ea + e)));
        }
    }
}

// =================================================================
// tf32 split + weight pre-split (unchanged)
// =================================================================
__device__ __forceinline__ void split_tf32(float v, uint32_t& hi, uint32_t& lo)
{
    asm("cvt.rna.tf32.f32 %0, %1;" : "=r"(hi) : "f"(v));
    float r = v - __uint_as_float(hi);
    asm("cvt.rna.tf32.f32 %0, %1;" : "=r"(lo) : "f"(r));
}

__global__ __launch_bounds__(256) void presplit_kernel(
    const float* __restrict__ m0, const float* __restrict__ m1, const float* __restrict__ m2,
    const float* __restrict__ m3, const float* __restrict__ m4, const float* __restrict__ m5,
    const float* __restrict__ m6, const float* __restrict__ m7, const float* __restrict__ m8,
    float* __restrict__ out)
{
    int idx = blockIdx.x * blockDim.x + threadIdx.x;
    if (idx >= 9 * 4096) return;
    int mat = idx >> 12;
    int j = idx & 4095;
    int k = j >> 6;
    int n = j & 63;

    const float* src;
    switch (mat) {
        case 0: src = m0; break; case 1: src = m1; break; case 2: src = m2; break;
        case 3: src = m3; break; case 4: src = m4; break; case 5: src = m5; break;
        case 6: src = m6; break; case 7: src = m7; break; default: src = m8; break;
    }
    uint32_t hi, lo;
    split_tf32(__ldg(src + j), hi, lo);
    float* dst = out + (size_t)mat * 2 * WSEG_FLOATS;
    dst[n * APAD + k]               = __uint_as_float(hi);
    dst[WSEG_FLOATS + n * APAD + k] = __uint_as_float(lo);
}

// =================================================================
// x -> fp16 conversion (one-time)
// =================================================================
__global__ __launch_bounds__(256) void cvt_half_kernel(const float* __restrict__ X,
                                                       __half* __restrict__ Xh, int total)
{
    int i = blockIdx.x * blockDim.x + threadIdx.x;
    int base = i * 8;
    if (base >= total) return;
    float4 a = *reinterpret_cast<const float4*>(X + base);
    float4 b = *reinterpret_cast<const float4*>(X + base + 4);
    __half2 h[4];
    h[0] = __float22half2_rn(make_float2(a.x, a.y));
    h[1] = __float22half2_rn(make_float2(a.z, a.w));
    h[2] = __float22half2_rn(make_float2(b.x, b.y));
    h[3] = __float22half2_rn(make_float2(b.z, b.w));
    *reinterpret_cast<uint4*>(Xh + base) = *reinterpret_cast<uint4*>(h);
}

// =================================================================
// fp16-gather aggregation (R11 shape, MLP widened to 4):
// warp per node, lane owns 2 channels; 4 independent meta loads +
// 4 independent gathers per iteration, plain indexed loads (no shfl).
// =================================================================
__global__ __launch_bounds__(256) void aggx_h_kernel(const int* __restrict__ off,
                                                     const int2* __restrict__ meta,
                                                     const __half* __restrict__ Xh,
                                                     __half* __restrict__ XEh,
                                                     __half* __restrict__ X1h, int N)
{
    int w = (blockIdx.x * blockDim.x + threadIdx.x) >> 5;
    int lane = threadIdx.x & 31;
    if (w >= N) return;

    int beg = __ldg(off + w);
    int end = __ldg(off + w + 1);

    float2 aE = make_float2(0.f, 0.f);
    float2 a1 = make_float2(0.f, 0.f);

    const __half2* X2 = reinterpret_cast<const __half2*>(Xh);

    int k = beg;
    for (; k + 4 <= end; k += 4) {
        int2 m0 = __ldg(meta + k);
        int2 m1 = __ldg(meta + k + 1);
        int2 m2 = __ldg(meta + k + 2);
        int2 m3 = __ldg(meta + k + 3);
        float2 v0 = __half22float2(X2[(size_t)m0.x * 32 + lane]);
        float2 v1 = __half22float2(X2[(size_t)m1.x * 32 + lane]);
        float2 v2 = __half22float2(X2[(size_t)m2.x * 32 + lane]);
        float2 v3 = __half22float2(X2[(size_t)m3.x * 32 + lane]);
        float e0 = __int_as_float(m0.y);
        float e1 = __int_as_float(m1.y);
        float e2 = __int_as_float(m2.y);
        float e3 = __int_as_float(m3.y);
        aE.x = fmaf(e0, v0.x, aE.x); aE.y = fmaf(e0, v0.y, aE.y);
        aE.x = fmaf(e1, v1.x, aE.x); aE.y = fmaf(e1, v1.y, aE.y);
        aE.x = fmaf(e2, v2.x, aE.x); aE.y = fmaf(e2, v2.y, aE.y);
        aE.x = fmaf(e3, v3.x, aE.x); aE.y = fmaf(e3, v3.y, aE.y);
        a1.x += (v0.x + v1.x) + (v2.x + v3.x);
        a1.y += (v0.y + v1.y) + (v2.y + v3.y);
    }
    for (; k < end; k++) {
        int2 m0 = __ldg(meta + k);
        float2 v0 = __half22float2(X2[(size_t)m0.x * 32 + lane]);
        float e0 = __int_as_float(m0.y);
        aE.x = fmaf(e0, v0.x, aE.x); aE.y = fmaf(e0, v0.y, aE.y);
        a1.x += v0.x;                a1.y += v0.y;
    }

    reinterpret_cast<__half2*>(XEh)[(size_t)w * 32 + lane] = __float22half2_rn(aE);
    reinterpret_cast<__half2*>(X1h)[(size_t)w * 32 + lane] = __float22half2_rn(a1);
}

// =================================================================
// TF32 tensor-core GEMM (unchanged from R11 winner)
// =================================================================
#define SA_FLOATS (128 * APAD)     /* 8704 */
#define TC_SMEM_FLOATS (SA_FLOATS + 2 * WSEG_FLOATS)
#define TC_SMEM_BYTES  (TC_SMEM_FLOATS * 4)   /* 69632 B */

__device__ __forceinline__ void mma_tf32(float* c, const uint32_t* a, const uint32_t* b)
{
    asm("mma.sync.aligned.m16n8k8.row.col.f32.tf32.tf32.f32 "
        "{%0,%1,%2,%3}, {%4,%5,%6,%7}, {%8,%9}, {%0,%1,%2,%3};"
        : "+f"(c[0]), "+f"(c[1]), "+f"(c[2]), "+f"(c[3])
        : "r"(a[0]), "r"(a[1]), "r"(a[2]), "r"(a[3]), "r"(b[0]), "r"(b[1]));
}

__global__ __launch_bounds__(256, 3) void gemm192_tc(const __half* __restrict__ XEh,
                                                     const __half* __restrict__ X1h,
                                                     const __half* __restrict__ Xh,
                                                     const float* __restrict__ Wsp,
                                                     const float* __restrict__ bias,
                                                     __half* __restrict__ Hh, int N)
{
    extern __shared__ float sm[];
    float* sA   = sm;
    float* sWhi = sm + SA_FLOATS;
    float* sWlo = sWhi + WSEG_FLOATS;

    const int tid  = threadIdx.x;
    const int lane = tid & 31;
    const int wid  = tid >> 5;
    const int grp  = lane >> 2;
    const int qid  = lane & 3;
    const int wm   = wid & 3;
    const int wn   = wid >> 2;
    const int row0 = blockIdx.x * 128;

    float c[2][4][4];
    #pragma unroll
    for (int mt = 0; mt < 2; mt++)
        #pragma unroll
        for (int nt = 0; nt < 4; nt++)
            #pragma unroll
            for (int j = 0; j < 4; j++) c[mt][nt][j] = 0.f;

    #pragma unroll
    for (int seg = 0; seg < 3; seg++) {
        const __half* A = (seg == 0) ? XEh : (seg == 1) ? X1h : Xh;
        const float* Wseg = Wsp + (size_t)seg * 2 * WSEG_FLOATS;

        if (seg > 0) __syncthreads();

        #pragma unroll
        for (int i = tid; i < 2048; i += 256) {
            int r  = i >> 4;
            int k4 = (i & 15) * 4;
            int row = row0 + r;
            float4 v = make_float4(0.f, 0.f, 0.f, 0.f);
            if (row < N) {
                uint2 hv = *reinterpret_cast<const uint2*>(A + (size_t)row * 64 + k4);
                float2 lo2 = __half22float2(*reinterpret_cast<__half2*>(&hv.x));
                float2 hi2 = __half22float2(*reinterpret_cast<__half2*>(&hv.y));
                v = make_float4(lo2.x, lo2.y, hi2.x, hi2.y);
            }
            *reinterpret_cast<float4*>(&sA[r * APAD + k4]) = v;
        }
        #pragma unroll
        for (int i = tid; i < 2176; i += 256) {
            float4 v = __ldg(reinterpret_cast<const float4*>(Wseg) + i);
            *reinterpret_cast<float4*>(&sWhi[i * 4]) = v;
        }
        __syncthreads();

        #pragma unroll
        for (int kst = 0; kst < 8; kst++) {
            const int k0 = kst * 8;

            uint32_t a[2][4];
            #pragma unroll
            for (int mt = 0; mt < 2; mt++) {
                int r0 = (wm * 32 + mt * 16 + grp) * APAD + k0 + qid;
                int r1 = r0 + 8 * APAD;
                a[mt][0] = __float_as_uint(sA[r0]);
                a[mt][1] = __float_as_uint(sA[r1]);
                a[mt][2] = __float_as_uint(sA[r0 + 4]);
                a[mt][3] = __float_as_uint(sA[r1 + 4]);
            }
            uint32_t bhi[4][2], blo[4][2];
            #pragma unroll
            for (int nt = 0; nt < 4; nt++) {
                int b0 = (wn * 32 + nt * 8 + grp) * APAD + k0 + qid;
                bhi[nt][0] = __float_as_uint(sWhi[b0]);
                bhi[nt][1] = __float_as_uint(sWhi[b0 + 4]);
                blo[nt][0] = __float_as_uint(sWlo[b0]);
                blo[nt][1] = __float_as_uint(sWlo[b0 + 4]);
            }

            #pragma unroll
            for (int mt = 0; mt < 2; mt++) {
                #pragma unroll
                for (int nt = 0; nt < 4; nt++) {
                    mma_tf32(c[mt][nt], a[mt], bhi[nt]);
                    mma_tf32(c[mt][nt], a[mt], blo[nt]);
                }
            }
        }
    }

    #pragma unroll
    for (int mt = 0; mt < 2; mt++) {
        int rbase = row0 + wm * 32 + mt * 16 + grp;
        #pragma unroll
        for (int nt = 0; nt < 4; nt++) {
            int col = wn * 32 + nt * 8 + 2 * qid;
            float2 b2 = __ldg(reinterpret_cast<const float2*>(bias + col));
            if (rbase < N) {
                float2 v = make_float2(fmaxf(c[mt][nt][0] + b2.x, 0.f),
                                       fmaxf(c[mt][nt][1] + b2.y, 0.f));
                *reinterpret_cast<__half2*>(Hh + (size_t)rbase * 64 + col) = __float22half2_rn(v);
            }
            if (rbase + 8 < N) {
                float2 v = make_float2(fmaxf(c[mt][nt][2] + b2.x, 0.f),
                                       fmaxf(c[mt][nt][3] + b2.y, 0.f));
                *reinterpret_cast<__half2*>(Hh + (size_t)(rbase + 8) * 64 + col) = __float22half2_rn(v);
            }
        }
    }
}

// =================================================================
// Layer 3 fully fused (R11 shape, MLP widened to 4)
// =================================================================
__global__ __launch_bounds__(256) void agg3_ls(const int* __restrict__ off,
                                               const int2* __restrict__ meta,
                                               const __half* __restrict__ HBh,
                                               const float* __restrict__ Wm,
                                               const float* __restrict__ Bm,
                                               const float* __restrict__ Wr,
                                               const float* __restrict__ b,
                                               float* __restrict__ OUT, int N)
{
    __shared__ float sw[768];
    int tid = threadIdx.x;
    if (tid < 256) { sw[tid] = Wm[tid]; sw[256 + tid] = Bm[tid]; sw[512 + tid] = Wr[tid]; }
    __syncthreads();

    int w = (blockIdx.x * blockDim.x + tid) >> 5;
    int lane = tid & 31;
    if (w >= N) return;

    int beg = __ldg(off + w);
    int end = __ldg(off + w + 1);

    float2 aE = make_float2(0.f, 0.f);
    float2 a1 = make_float2(0.f, 0.f);

    const __half2* X2 = reinterpret_cast<const __half2*>(HBh);

    int k = beg;
    for (; k + 4 <= end; k += 4) {
        int2 m0 = __ldg(meta + k);
        int2 m1 = __ldg(meta + k + 1);
        int2 m2 = __ldg(meta + k + 2);
        int2 m3 = __ldg(meta + k + 3);
        float2 v0 = __half22float2(X2[(size_t)m0.x * 32 + lane]);
        float2 v1 = __half22float2(X2[(size_t)m1.x * 32 + lane]);
        float2 v2 = __half22float2(X2[(size_t)m2.x * 32 + lane]);
        float2 v3 = __half22float2(X2[(size_t)m3.x * 32 + lane]);
        float e0 = __int_as_float(m0.y);
        float e1 = __int_as_float(m1.y);
        float e2 = __int_as_float(m2.y);
        float e3 = __int_as_float(m3.y);
        aE.x = fmaf(e0, v0.x, aE.x); aE.y = fmaf(e0, v0.y, aE.y);
        aE.x = fmaf(e1, v1.x, aE.x); aE.y = fmaf(e1, v1.y, aE.y);
        aE.x = fmaf(e2, v2.x, aE.x); aE.y = fmaf(e2, v2.y, aE.y);
        aE.x = fmaf(e3, v3.x, aE.x); aE.y = fmaf(e3, v3.y, aE.y);
        a1.x += (v0.x + v1.x) + (v2.x + v3.x);
        a1.y += (v0.y + v1.y) + (v2.y + v3.y);
    }
    for (; k < end; k++) {
        int2 m0 = __ldg(meta + k);
        float2 v0 = __half22float2(X2[(size_t)m0.x * 32 + lane]);
        float e0 = __int_as_float(m0.y);
        aE.x = fmaf(e0, v0.x, aE.x); aE.y = fmaf(e0, v0.y, aE.y);
        a1.x += v0.x;                a1.y += v0.y;
    }

    float2 hb = __half22float2(X2[(size_t)w * 32 + lane]);

    const int k0 = lane * 2 * 4;
    float p[4];
    #pragma unroll
    for (int c = 0; c < 4; c++) {
        float v = aE.x * sw[k0 + c] + aE.y * sw[k0 + 4 + c];
        v = fmaf(a1.x, sw[256 + k0 + c], v);
        v = fmaf(a1.y, sw[256 + k0 + 4 + c], v);
        v = fmaf(hb.x, sw[512 + k0 + c], v);
        v = fmaf(hb.y, sw[512 + k0 + 4 + c], v);
        p[c] = v;
    }
    #pragma unroll
    for (int d = 16; d > 0; d >>= 1) {
        p[0] += __shfl_xor_sync(0xFFFFFFFFu, p[0], d);
        p[1] += __shfl_xor_sync(0xFFFFFFFFu, p[1], d);
        p[2] += __shfl_xor_sync(0xFFFFFFFFu, p[2], d);
        p[3] += __shfl_xor_sync(0xFFFFFFFFu, p[3], d);
    }

    if (lane == 0) {
        #pragma unroll
        for (int c = 0; c < 4; c++) p[c] += __ldg(b + c);
        float m = fmaxf(fmaxf(p[0], p[1]), fmaxf(p[2], p[3]));
        float s = __expf(p[0] - m) + __expf(p[1] - m) +
                  __expf(p[2] - m) + __expf(p[3] - m);
        float lse = m + __logf(s);
        float4 o;
        o.x = p[0] - lse; o.y = p[1] - lse; o.z = p[2] - lse; o.w = p[3] - lse;
        *reinterpret_cast<float4*>(OUT + (size_t)w * 4) = o;
    }
}

// =================================================================
extern "C" void kernel_launch(void* const* d_in, const int* in_sizes, int n_in,
                              void* d_out, int out_size)
{
    const float* x   = (const float*)d_in[0];
    const int*   ei  = (const int*)  d_in[1];
    const float* ea  = (const float*)d_in[2];
    const float* We1 = (const float*)d_in[3];
    const float* be1 = (const float*)d_in[4];
    const float* Wr1 = (const float*)d_in[5];
    const float* b1  = (const float*)d_in[6];
    const float* We2 = (const float*)d_in[7];
    const float* be2 = (const float*)d_in[8];
    const float* Wr2 = (const float*)d_in[9];
    const float* b2  = (const float*)d_in[10];
    const float* We3 = (const float*)d_in[11];
    const float* be3 = (const float*)d_in[12];
    const float* Wr3 = (const float*)d_in[13];
    const float* b3  = (const float*)d_in[14];

    const int N = in_sizes[0] / DIN;
    const int E = in_sizes[2];

    float *Wsp, *OUT = (float*)d_out;
    __half *XEh, *X1h, *Xh, *HAh, *HBh;
    int *counts, *off, *cursor, *bsum, *boff;
    int2 *meta;
    cudaGetSymbolAddress((void**)&XEh, g_XEh);
    cudaGetSymbolAddress((void**)&X1h, g_X1h);
    cudaGetSymbolAddress((void**)&Xh, g_Xh);
    cudaGetSymbolAddress((void**)&HAh, g_HAh);
    cudaGetSymbolAddress((void**)&HBh, g_HBh);
    cudaGetSymbolAddress((void**)&Wsp, g_Wsp);
    cudaGetSymbolAddress((void**)&counts, g_counts);
    cudaGetSymbolAddress((void**)&off, g_off);
    cudaGetSymbolAddress((void**)&cursor, g_cursor);
    cudaGetSymbolAddress((void**)&bsum, g_bsum);
    cudaGetSymbolAddress((void**)&boff, g_boff);
    cudaGetSymbolAddress((void**)&meta, g_meta);

    cudaFuncSetAttribute(gemm192_tc, cudaFuncAttributeMaxDynamicSharedMemorySize, TC_SMEM_BYTES);

    const int edge4Grid = (E / 4 + 256) / 256;
    const int rowGrid   = (N + 255) / 256;
    const int aggGrid   = (N * 32 + 255) / 256;
    const int tcGrid    = (N + 127) / 128;
    const int scanGrid  = (N + 2047) / 2048;
    const int cvtGrid   = (N * 64 / 8 + 255) / 256;

    // ---- CSR build + weight pre-split + x->fp16 ----
    zero_kernel<<<rowGrid, 256>>>(counts, N);
    hist_kernel<<<edge4Grid, 256>>>(ei, counts, E);
    scanA_kernel<<<scanGrid, 256>>>(counts, bsum, N);
    scanB_kernel<<<1, 64>>>(bsum, boff, off, scanGrid, N);
    scanC_kernel<<<scanGrid, 256>>>(counts, boff, off, cursor, N);
    scatter_kernel<<<edge4Grid, 256>>>(ei, ea, cursor, meta, E);
    presplit_kernel<<<144, 256>>>(We1, be1, Wr1, We2, be2, Wr2, We3, be3, Wr3, Wsp);
    cvt_half_kernel<<<cvtGrid, 256>>>(x, Xh, N * 64);

    // ---- layer 1 ----
    aggx_h_kernel<<<aggGrid, 256>>>(off, meta, Xh, XEh, X1h, N);
    gemm192_tc<<<tcGrid, 256, TC_SMEM_BYTES>>>(XEh, X1h, Xh, Wsp, b1, HAh, N);

    // ---- layer 2 ----
    aggx_h_kernel<<<aggGrid, 256>>>(off, meta, HAh, XEh, X1h, N);
    gemm192_tc<<<tcGrid, 256, TC_SMEM_BYTES>>>(XEh, X1h, HAh,
                                               Wsp + (size_t)3 * 2 * WSEG_FLOATS, b2, HBh, N);

    // ---- layer 3 (fully fused) ----
    agg3_ls<<<aggGrid, 256>>>(off, meta, HBh, We3, be3, Wr3, b3, OUT, N);
}

// round 14
// speedup vs baseline: 1.0167x; 1.0155x over previous
#include <cuda_runtime.h>
#include <cuda_fp16.h>
#include <cstdint>

#define MAXN 100000
#define MAXE 1600000
#define DIN  64

// ---------------- scratch (no cudaMalloc allowed) ----------------
__device__ __half g_XEh[(size_t)MAXN * 64];  // sum of e * X[src] per dst (fp16)
__device__ __half g_X1h[(size_t)MAXN * 64];  // sum of X[src] per dst (fp16)
__device__ __half g_Xh[(size_t)MAXN * 64];   // fp16 copy of input x
__device__ __half g_HAh[(size_t)MAXN * 64];  // relu(layer1 out), fp16
__device__ __half g_HBh[(size_t)MAXN * 64];  // relu(layer2 out), fp16
__device__ int    g_counts[MAXN];
__device__ int    g_off[MAXN + 1];
__device__ int    g_cursor[MAXN];
__device__ int    g_bsum[64];
__device__ int    g_boff[64];
__device__ unsigned g_meta[MAXE];            // packed: e_q15 << 17 | src  (grouped by dst)

#define EQ_SCALE   32768.0f
#define EQ_INV     (1.0f / 32768.0f)
#define SRC_MASK   0x1FFFFu

// pre-split tf32 weights: [mat 0..8][hi/lo][n*68+k]
#define APAD 68
#define WSEG_FLOATS (64 * APAD)              /* 4352 */
__device__ float g_Wsp[9 * 2 * WSEG_FLOATS];

// =================================================================
// CSR build
// =================================================================
__global__ void zero_kernel(int* __restrict__ counts, int N)
{
    int i = blockIdx.x * blockDim.x + threadIdx.x;
    if (i < N) counts[i] = 0;
}

__global__ void hist_kernel(const int* __restrict__ ei, int* __restrict__ counts, int E)
{
    int i = blockIdx.x * blockDim.x + threadIdx.x;
    int base = i * 4;
    if (base >= E) return;
    if (((E & 3) == 0) && (base + 4 <= E)) {
        int4 d = *reinterpret_cast<const int4*>(ei + E + base);
        atomicAdd(&counts[d.x], 1);
        atomicAdd(&counts[d.y], 1);
        atomicAdd(&counts[d.z], 1);
        atomicAdd(&counts[d.w], 1);
    } else {
        int hi = min(base + 4, E);
        for (int e = base; e < hi; e++) atomicAdd(&counts[__ldg(ei + E + e)], 1);
    }
}

__global__ __launch_bounds__(256) void scanA_kernel(const int* __restrict__ counts,
                                                    int* __restrict__ bsum, int N)
{
    __shared__ int red[256];
    int tid = threadIdx.x;
    int base = blockIdx.x * 2048 + tid * 8;
    int s = 0;
    if (base < N) {
        int4 a = *reinterpret_cast<const int4*>(counts + base);
        int4 b = *reinterpret_cast<const int4*>(counts + base + 4);
        s = a.x + a.y + a.z + a.w + b.x + b.y + b.z + b.w;
    }
    red[tid] = s;
    __syncthreads();
    #pragma unroll
    for (int d = 128; d > 0; d >>= 1) {
        if (tid < d) red[tid] += red[tid + d];
        __syncthreads();
    }
    if (tid == 0) bsum[blockIdx.x] = red[0];
}

__global__ __launch_bounds__(64) void scanB_kernel(const int* __restrict__ bsum,
                                                   int* __restrict__ boff,
                                                   int* __restrict__ off, int B, int N)
{
    __shared__ int sh[64];
    int tid = threadIdx.x;
    int v = (tid < B) ? bsum[tid] : 0;
    sh[tid] = v;
    __syncthreads();
    #pragma unroll
    for (int d = 1; d < 64; d <<= 1) {
        int t = (tid >= d) ? sh[tid - d] : 0;
        __syncthreads();
        sh[tid] += t;
        __syncthreads();
    }
    boff[tid] = sh[tid] - v;
    if (tid == 63) off[N] = sh[63];
}

__global__ __launch_bounds__(256) void scanC_kernel(const int* __restrict__ counts,
                                                    const int* __restrict__ boff,
                                                    int* __restrict__ off,
                                                    int* __restrict__ cursor, int N)
{
    __shared__ int wsum[8], woff[8];
    int tid = threadIdx.x;
    int lane = tid & 31;
    int warp = tid >> 5;
    int base = blockIdx.x * 2048 + tid * 8;

    int4 a = make_int4(0, 0, 0, 0), b = make_int4(0, 0, 0, 0);
    if (base < N) {
        a = *reinterpret_cast<const int4*>(counts + base);
        b = *reinterpret_cast<const int4*>(counts + base + 4);
    }
    int s = a.x + a.y + a.z + a.w + b.x + b.y + b.z + b.w;

    int incl = s;
    #pragma unroll
    for (int d = 1; d < 32; d <<= 1) {
        int t = __shfl_up_sync(0xFFFFFFFFu, incl, d);
        if (lane >= d) incl += t;
    }
    if (lane == 31) wsum[warp] = incl;
    __syncthreads();
    if (tid == 0) {
        int run = 0;
        #pragma unroll
        for (int j = 0; j < 8; j++) { int t = wsum[j]; woff[j] = run; run += t; }
    }
    __syncthreads();

    int ex = __ldg(boff + blockIdx.x) + woff[warp] + (incl - s);
    if (base < N) {
        int o0 = ex;
        int o1 = o0 + a.x, o2 = o1 + a.y, o3 = o2 + a.z, o4 = o3 + a.w;
        int o5 = o4 + b.x, o6 = o5 + b.y, o7 = o6 + b.z;
        int4 oa = make_int4(o0, o1, o2, o3);
        int4 ob = make_int4(o4, o5, o6, o7);
        *reinterpret_cast<int4*>(off + base)        = oa;
        *reinterpret_cast<int4*>(off + base + 4)    = ob;
        *reinterpret_cast<int4*>(cursor + base)     = oa;
        *reinterpret_cast<int4*>(cursor + base + 4) = ob;
    }
}

__device__ __forceinline__ unsigned pack_meta(int s, float e)
{
    unsigned eq = (unsigned)__float2int_rn(e * EQ_SCALE);
    eq = min(eq, 32767u);
    return (eq << 17) | (unsigned)s;
}

__global__ void scatter_kernel(const int* __restrict__ ei, const float* __restrict__ ea,
                               int* __restrict__ cursor, unsigned* __restrict__ meta, int E)
{
    int i = blockIdx.x * blockDim.x + threadIdx.x;
    int base = i * 4;
    if (base >= E) return;
    if (((E & 3) == 0) && (base + 4 <= E)) {
        int4 s4 = *reinterpret_cast<const int4*>(ei + base);
        int4 d4 = *reinterpret_cast<const int4*>(ei + E + base);
        float4 e4 = *reinterpret_cast<const float4*>(ea + base);
        int p0 = atomicAdd(&cursor[d4.x], 1);
        int p1 = atomicAdd(&cursor[d4.y], 1);
        int p2 = atomicAdd(&cursor[d4.z], 1);
        int p3 = atomicAdd(&cursor[d4.w], 1);
        meta[p0] = pack_meta(s4.x, e4.x);
        meta[p1] = pack_meta(s4.y, e4.y);
        meta[p2] = pack_meta(s4.z, e4.z);
        meta[p3] = pack_meta(s4.w, e4.w);
    } else {
        int hi = min(base + 4, E);
        for (int e = base; e < hi; e++) {
            int s = __ldg(ei + e);
            int d = __ldg(ei + E + e);
            int pos = atomicAdd(&cursor[d], 1);
            meta[pos] = pack_meta(s, __ldg(ea + e));
        }
    }
}

// =================================================================
// tf32 split + weight pre-split (unchanged)
// =================================================================
__device__ __forceinline__ void split_tf32(float v, uint32_t& hi, uint32_t& lo)
{
    asm("cvt.rna.tf32.f32 %0, %1;" : "=r"(hi) : "f"(v));
    float r = v - __uint_as_float(hi);
    asm("cvt.rna.tf32.f32 %0, %1;" : "=r"(lo) : "f"(r));
}

__global__ __launch_bounds__(256) void presplit_kernel(
    const float* __restrict__ m0, const float* __restrict__ m1, const float* __restrict__ m2,
    const float* __restrict__ m3, const float* __restrict__ m4, const float* __restrict__ m5,
    const float* __restrict__ m6, const float* __restrict__ m7, const float* __restrict__ m8,
    float* __restrict__ out)
{
    int idx = blockIdx.x * blockDim.x + threadIdx.x;
    if (idx >= 9 * 4096) return;
    int mat = idx >> 12;
    int j = idx & 4095;
    int k = j >> 6;
    int n = j & 63;

    const float* src;
    switch (mat) {
        case 0: src = m0; break; case 1: src = m1; break; case 2: src = m2; break;
        case 3: src = m3; break; case 4: src = m4; break; case 5: src = m5; break;
        case 6: src = m6; break; case 7: src = m7; break; default: src = m8; break;
    }
    uint32_t hi, lo;
    split_tf32(__ldg(src + j), hi, lo);
    float* dst = out + (size_t)mat * 2 * WSEG_FLOATS;
    dst[n * APAD + k]               = __uint_as_float(hi);
    dst[WSEG_FLOATS + n * APAD + k] = __uint_as_float(lo);
}

// =================================================================
// x -> fp16 conversion (one-time)
// =================================================================
__global__ __launch_bounds__(256) void cvt_half_kernel(const float* __restrict__ X,
                                                       __half* __restrict__ Xh, int total)
{
    int i = blockIdx.x * blockDim.x + threadIdx.x;
    int base = i * 8;
    if (base >= total) return;
    float4 a = *reinterpret_cast<const float4*>(X + base);
    float4 b = *reinterpret_cast<const float4*>(X + base + 4);
    __half2 h[4];
    h[0] = __float22half2_rn(make_float2(a.x, a.y));
    h[1] = __float22half2_rn(make_float2(a.z, a.w));
    h[2] = __float22half2_rn(make_float2(b.x, b.y));
    h[3] = __float22half2_rn(make_float2(b.z, b.w));
    *reinterpret_cast<uint4*>(Xh + base) = *reinterpret_cast<uint4*>(h);
}

// =================================================================
// fp16-gather aggregation (R11 winner loop shape: unroll-2),
// packed 4B meta. warp per node, lane owns 2 channels.
// =================================================================
__global__ __launch_bounds__(256) void aggx_h_kernel(const int* __restrict__ off,
                                                     const unsigned* __restrict__ meta,
                                                     const __half* __restrict__ Xh,
                                                     __half* __restrict__ XEh,
                                                     __half* __restrict__ X1h, int N)
{
    int w = (blockIdx.x * blockDim.x + threadIdx.x) >> 5;
    int lane = threadIdx.x & 31;
    if (w >= N) return;

    int beg = __ldg(off + w);
    int end = __ldg(off + w + 1);

    float2 aE = make_float2(0.f, 0.f);
    float2 a1 = make_float2(0.f, 0.f);

    const __half2* X2 = reinterpret_cast<const __half2*>(Xh);

    int k = beg;
    for (; k + 2 <= end; k += 2) {
        unsigned m0 = __ldg(meta + k);
        unsigned m1 = __ldg(meta + k + 1);
        float2 v0 = __half22float2(X2[(size_t)(m0 & SRC_MASK) * 32 + lane]);
        float2 v1 = __half22float2(X2[(size_t)(m1 & SRC_MASK) * 32 + lane]);
        float e0 = (float)(m0 >> 17) * EQ_INV;
        float e1 = (float)(m1 >> 17) * EQ_INV;
        aE.x = fmaf(e0, v0.x, aE.x); aE.y = fmaf(e0, v0.y, aE.y);
        aE.x = fmaf(e1, v1.x, aE.x); aE.y = fmaf(e1, v1.y, aE.y);
        a1.x += v0.x + v1.x;         a1.y += v0.y + v1.y;
    }
    if (k < end) {
        unsigned m0 = __ldg(meta + k);
        float2 v0 = __half22float2(X2[(size_t)(m0 & SRC_MASK) * 32 + lane]);
        float e0 = (float)(m0 >> 17) * EQ_INV;
        aE.x = fmaf(e0, v0.x, aE.x); aE.y = fmaf(e0, v0.y, aE.y);
        a1.x += v0.x;                a1.y += v0.y;
    }

    reinterpret_cast<__half2*>(XEh)[(size_t)w * 32 + lane] = __float22half2_rn(aE);
    reinterpret_cast<__half2*>(X1h)[(size_t)w * 32 + lane] = __float22half2_rn(a1);
}

// =================================================================
// TF32 tensor-core GEMM (unchanged from R11 winner)
// =================================================================
#define SA_FLOATS (128 * APAD)     /* 8704 */
#define TC_SMEM_FLOATS (SA_FLOATS + 2 * WSEG_FLOATS)
#define TC_SMEM_BYTES  (TC_SMEM_FLOATS * 4)   /* 69632 B */

__device__ __forceinline__ void mma_tf32(float* c, const uint32_t* a, const uint32_t* b)
{
    asm("mma.sync.aligned.m16n8k8.row.col.f32.tf32.tf32.f32 "
        "{%0,%1,%2,%3}, {%4,%5,%6,%7}, {%8,%9}, {%0,%1,%2,%3};"
        : "+f"(c[0]), "+f"(c[1]), "+f"(c[2]), "+f"(c[3])
        : "r"(a[0]), "r"(a[1]), "r"(a[2]), "r"(a[3]), "r"(b[0]), "r"(b[1]));
}

__global__ __launch_bounds__(256, 3) void gemm192_tc(const __half* __restrict__ XEh,
                                                     const __half* __restrict__ X1h,
                                                     const __half* __restrict__ Xh,
                                                     const float* __restrict__ Wsp,
                                                     const float* __restrict__ bias,
                                                     __half* __restrict__ Hh, int N)
{
    extern __shared__ float sm[];
    float* sA   = sm;
    float* sWhi = sm + SA_FLOATS;
    float* sWlo = sWhi + WSEG_FLOATS;

    const int tid  = threadIdx.x;
    const int lane = tid & 31;
    const int wid  = tid >> 5;
    const int grp  = lane >> 2;
    const int qid  = lane & 3;
    const int wm   = wid & 3;
    const int wn   = wid >> 2;
    const int row0 = blockIdx.x * 128;

    float c[2][4][4];
    #pragma unroll
    for (int mt = 0; mt < 2; mt++)
        #pragma unroll
        for (int nt = 0; nt < 4; nt++)
            #pragma unroll
            for (int j = 0; j < 4; j++) c[mt][nt][j] = 0.f;

    #pragma unroll
    for (int seg = 0; seg < 3; seg++) {
        const __half* A = (seg == 0) ? XEh : (seg == 1) ? X1h : Xh;
        const float* Wseg = Wsp + (size_t)seg * 2 * WSEG_FLOATS;

        if (seg > 0) __syncthreads();

        #pragma unroll
        for (int i = tid; i < 2048; i += 256) {
            int r  = i >> 4;
            int k4 = (i & 15) * 4;
            int row = row0 + r;
            float4 v = make_float4(0.f, 0.f, 0.f, 0.f);
            if (row < N) {
                uint2 hv = *reinterpret_cast<const uint2*>(A + (size_t)row * 64 + k4);
                float2 lo2 = __half22float2(*reinterpret_cast<__half2*>(&hv.x));
                float2 hi2 = __half22float2(*reinterpret_cast<__half2*>(&hv.y));
                v = make_float4(lo2.x, lo2.y, hi2.x, hi2.y);
            }
            *reinterpret_cast<float4*>(&sA[r * APAD + k4]) = v;
        }
        #pragma unroll
        for (int i = tid; i < 2176; i += 256) {
            float4 v = __ldg(reinterpret_cast<const float4*>(Wseg) + i);
            *reinterpret_cast<float4*>(&sWhi[i * 4]) = v;
        }
        __syncthreads();

        #pragma unroll
        for (int kst = 0; kst < 8; kst++) {
            const int k0 = kst * 8;

            uint32_t a[2][4];
            #pragma unroll
            for (int mt = 0; mt < 2; mt++) {
                int r0 = (wm * 32 + mt * 16 + grp) * APAD + k0 + qid;
                int r1 = r0 + 8 * APAD;
                a[mt][0] = __float_as_uint(sA[r0]);
                a[mt][1] = __float_as_uint(sA[r1]);
                a[mt][2] = __float_as_uint(sA[r0 + 4]);
                a[mt][3] = __float_as_uint(sA[r1 + 4]);
            }
            uint32_t bhi[4][2], blo[4][2];
            #pragma unroll
            for (int nt = 0; nt < 4; nt++) {
                int b0 = (wn * 32 + nt * 8 + grp) * APAD + k0 + qid;
                bhi[nt][0] = __float_as_uint(sWhi[b0]);
                bhi[nt][1] = __float_as_uint(sWhi[b0 + 4]);
                blo[nt][0] = __float_as_uint(sWlo[b0]);
                blo[nt][1] = __float_as_uint(sWlo[b0 + 4]);
            }

            #pragma unroll
            for (int mt = 0; mt < 2; mt++) {
                #pragma unroll
                for (int nt = 0; nt < 4; nt++) {
                    mma_tf32(c[mt][nt], a[mt], bhi[nt]);
                    mma_tf32(c[mt][nt], a[mt], blo[nt]);
                }
            }
        }
    }

    #pragma unroll
    for (int mt = 0; mt < 2; mt++) {
        int rbase = row0 + wm * 32 + mt * 16 + grp;
        #pragma unroll
        for (int nt = 0; nt < 4; nt++) {
            int col = wn * 32 + nt * 8 + 2 * qid;
            float2 b2 = __ldg(reinterpret_cast<const float2*>(bias + col));
            if (rbase < N) {
                float2 v = make_float2(fmaxf(c[mt][nt][0] + b2.x, 0.f),
                                       fmaxf(c[mt][nt][1] + b2.y, 0.f));
                *reinterpret_cast<__half2*>(Hh + (size_t)rbase * 64 + col) = __float22half2_rn(v);
            }
            if (rbase + 8 < N) {
                float2 v = make_float2(fmaxf(c[mt][nt][2] + b2.x, 0.f),
                                       fmaxf(c[mt][nt][3] + b2.y, 0.f));
                *reinterpret_cast<__half2*>(Hh + (size_t)(rbase + 8) * 64 + col) = __float22half2_rn(v);
            }
        }
    }
}

// =================================================================
// Layer 3 fully fused (R11 winner loop shape, packed meta)
// =================================================================
__global__ __launch_bounds__(256) void agg3_ls(const int* __restrict__ off,
                                               const unsigned* __restrict__ meta,
                                               const __half* __restrict__ HBh,
                                               const float* __restrict__ Wm,
                                               const float* __restrict__ Bm,
                                               const float* __restrict__ Wr,
                                               const float* __restrict__ b,
                                               float* __restrict__ OUT, int N)
{
    __shared__ float sw[768];
    int tid = threadIdx.x;
    if (tid < 256) { sw[tid] = Wm[tid]; sw[256 + tid] = Bm[tid]; sw[512 + tid] = Wr[tid]; }
    __syncthreads();

    int w = (blockIdx.x * blockDim.x + tid) >> 5;
    int lane = tid & 31;
    if (w >= N) return;

    int beg = __ldg(off + w);
    int end = __ldg(off + w + 1);

    float2 aE = make_float2(0.f, 0.f);
    float2 a1 = make_float2(0.f, 0.f);

    const __half2* X2 = reinterpret_cast<const __half2*>(HBh);

    int k = beg;
    for (; k + 2 <= end; k += 2) {
        unsigned m0 = __ldg(meta + k);
        unsigned m1 = __ldg(meta + k + 1);
        float2 v0 = __half22float2(X2[(size_t)(m0 & SRC_MASK) * 32 + lane]);
        float2 v1 = __half22float2(X2[(size_t)(m1 & SRC_MASK) * 32 + lane]);
        float e0 = (float)(m0 >> 17) * EQ_INV;
        float e1 = (float)(m1 >> 17) * EQ_INV;
        aE.x = fmaf(e0, v0.x, aE.x); aE.y = fmaf(e0, v0.y, aE.y);
        aE.x = fmaf(e1, v1.x, aE.x); aE.y = fmaf(e1, v1.y, aE.y);
        a1.x += v0.x + v1.x;         a1.y += v0.y + v1.y;
    }
    if (k < end) {
        unsigned m0 = __ldg(meta + k);
        float2 v0 = __half22float2(X2[(size_t)(m0 & SRC_MASK) * 32 + lane]);
        float e0 = (float)(m0 >> 17) * EQ_INV;
        aE.x = fmaf(e0, v0.x, aE.x); aE.y = fmaf(e0, v0.y, aE.y);
        a1.x += v0.x;                a1.y += v0.y;
    }

    float2 hb = __half22float2(X2[(size_t)w * 32 + lane]);

    const int k0 = lane * 2 * 4;
    float p[4];
    #pragma unroll
    for (int c = 0; c < 4; c++) {
        float v = aE.x * sw[k0 + c] + aE.y * sw[k0 + 4 + c];
        v = fmaf(a1.x, sw[256 + k0 + c], v);
        v = fmaf(a1.y, sw[256 + k0 + 4 + c], v);
        v = fmaf(hb.x, sw[512 + k0 + c], v);
        v = fmaf(hb.y, sw[512 + k0 + 4 + c], v);
        p[c] = v;
    }
    #pragma unroll
    for (int d = 16; d > 0; d >>= 1) {
        p[0] += __shfl_xor_sync(0xFFFFFFFFu, p[0], d);
        p[1] += __shfl_xor_sync(0xFFFFFFFFu, p[1], d);
        p[2] += __shfl_xor_sync(0xFFFFFFFFu, p[2], d);
        p[3] += __shfl_xor_sync(0xFFFFFFFFu, p[3], d);
    }

    if (lane == 0) {
        #pragma unroll
        for (int c = 0; c < 4; c++) p[c] += __ldg(b + c);
        float m = fmaxf(fmaxf(p[0], p[1]), fmaxf(p[2], p[3]));
        float s = __expf(p[0] - m) + __expf(p[1] - m) +
                  __expf(p[2] - m) + __expf(p[3] - m);
        float lse = m + __logf(s);
        float4 o;
        o.x = p[0] - lse; o.y = p[1] - lse; o.z = p[2] - lse; o.w = p[3] - lse;
        *reinterpret_cast<float4*>(OUT + (size_t)w * 4) = o;
    }
}

// =================================================================
extern "C" void kernel_launch(void* const* d_in, const int* in_sizes, int n_in,
                              void* d_out, int out_size)
{
    const float* x   = (const float*)d_in[0];
    const int*   ei  = (const int*)  d_in[1];
    const float* ea  = (const float*)d_in[2];
    const float* We1 = (const float*)d_in[3];
    const float* be1 = (const float*)d_in[4];
    const float* Wr1 = (const float*)d_in[5];
    const float* b1  = (const float*)d_in[6];
    const float* We2 = (const float*)d_in[7];
    const float* be2 = (const float*)d_in[8];
    const float* Wr2 = (const float*)d_in[9];
    const float* b2  = (const float*)d_in[10];
    const float* We3 = (const float*)d_in[11];
    const float* be3 = (const float*)d_in[12];
    const float* Wr3 = (const float*)d_in[13];
    const float* b3  = (const float*)d_in[14];

    const int N = in_sizes[0] / DIN;
    const int E = in_sizes[2];

    float *Wsp, *OUT = (float*)d_out;
    __half *XEh, *X1h, *Xh, *HAh, *HBh;
    int *counts, *off, *cursor, *bsum, *boff;
    unsigned *meta;
    cudaGetSymbolAddress((void**)&XEh, g_XEh);
    cudaGetSymbolAddress((void**)&X1h, g_X1h);
    cudaGetSymbolAddress((void**)&Xh, g_Xh);
    cudaGetSymbolAddress((void**)&HAh, g_HAh);
    cudaGetSymbolAddress((void**)&HBh, g_HBh);
    cudaGetSymbolAddress((void**)&Wsp, g_Wsp);
    cudaGetSymbolAddress((void**)&counts, g_counts);
    cudaGetSymbolAddress((void**)&off, g_off);
    cudaGetSymbolAddress((void**)&cursor, g_cursor);
    cudaGetSymbolAddress((void**)&bsum, g_bsum);
    cudaGetSymbolAddress((void**)&boff, g_boff);
    cudaGetSymbolAddress((void**)&meta, g_meta);

    cudaFuncSetAttribute(gemm192_tc, cudaFuncAttributeMaxDynamicSharedMemorySize, TC_SMEM_BYTES);

    const int edge4Grid = (E / 4 + 256) / 256;
    const int rowGrid   = (N + 255) / 256;
    const int aggGrid   = (N * 32 + 255) / 256;
    const int tcGrid    = (N + 127) / 128;
    const int scanGrid  = (N + 2047) / 2048;
    const int cvtGrid   = (N * 64 / 8 + 255) / 256;

    // ---- CSR build + weight pre-split + x->fp16 ----
    zero_kernel<<<rowGrid, 256>>>(counts, N);
    hist_kernel<<<edge4Grid, 256>>>(ei, counts, E);
    scanA_kernel<<<scanGrid, 256>>>(counts, bsum, N);
    scanB_kernel<<<1, 64>>>(bsum, boff, off, scanGrid, N);
    scanC_kernel<<<scanGrid, 256>>>(counts, boff, off, cursor, N);
    scatter_kernel<<<edge4Grid, 256>>>(ei, ea, cursor, meta, E);
    presplit_kernel<<<144, 256>>>(We1, be1, Wr1, We2, be2, Wr2, We3, be3, Wr3, Wsp);
    cvt_half_kernel<<<cvtGrid, 256>>>(x, Xh, N * 64);

    // ---- layer 1 ----
    aggx_h_kernel<<<aggGrid, 256>>>(off, meta, Xh, XEh, X1h, N);
    gemm192_tc<<<tcGrid, 256, TC_SMEM_BYTES>>>(XEh, X1h, Xh, Wsp, b1, HAh, N);

    // ---- layer 2 ----
    aggx_h_kernel<<<aggGrid, 256>>>(off, meta, HAh, XEh, X1h, N);
    gemm192_tc<<<tcGrid, 256, TC_SMEM_BYTES>>>(XEh, X1h, HAh,
                                               Wsp + (size_t)3 * 2 * WSEG_FLOATS, b2, HBh, N);

    // ---- layer 3 (fully fused) ----
    agg3_ls<<<aggGrid, 256>>>(off, meta, HBh, We3, be3, Wr3, b3, OUT, N);
}

// round 15
// speedup vs baseline: 1.1498x; 1.1309x over previous
#include <cuda_runtime.h>
#include <cuda_fp16.h>
#include <cstdint>

#define MAXN 100000
#define MAXE 1600000
#define DIN  64

// ---------------- scratch (no cudaMalloc allowed) ----------------
__device__ __half g_XEh[(size_t)MAXN * 64];  // sum of e * X[src] per dst (fp16)
__device__ __half g_X1h[(size_t)MAXN * 64];  // sum of X[src] per dst (fp16)
__device__ __half g_Xh[(size_t)MAXN * 64];   // fp16 copy of input x
__device__ __half g_HAh[(size_t)MAXN * 64];  // relu(layer1 out), fp16
__device__ __half g_HBh[(size_t)MAXN * 64];  // relu(layer2 out), fp16
__device__ float  g_PQ3[(size_t)MAXN * 8];   // layer3 P|Q per node (fp32)
__device__ int    g_counts[MAXN];
__device__ int    g_off[MAXN + 1];
__device__ int    g_cursor[MAXN];
__device__ int    g_bsum[64];
__device__ int    g_boff[64];
__device__ int2   g_meta[MAXE];              // {src, bits(e)} grouped by dst

// pre-split tf32 weights: [mat 0..8][hi/lo][n*68+k]
#define APAD 68
#define WSEG_FLOATS (64 * APAD)              /* 4352 */
__device__ float g_Wsp[9 * 2 * WSEG_FLOATS];

// =================================================================
// CSR build (R11 winner, unchanged)
// =================================================================
__global__ void zero_kernel(int* __restrict__ counts, int N)
{
    int i = blockIdx.x * blockDim.x + threadIdx.x;
    if (i < N) counts[i] = 0;
}

__global__ void hist_kernel(const int* __restrict__ ei, int* __restrict__ counts, int E)
{
    int i = blockIdx.x * blockDim.x + threadIdx.x;
    int base = i * 4;
    if (base >= E) return;
    if (((E & 3) == 0) && (base + 4 <= E)) {
        int4 d = *reinterpret_cast<const int4*>(ei + E + base);
        atomicAdd(&counts[d.x], 1);
        atomicAdd(&counts[d.y], 1);
        atomicAdd(&counts[d.z], 1);
        atomicAdd(&counts[d.w], 1);
    } else {
        int hi = min(base + 4, E);
        for (int e = base; e < hi; e++) atomicAdd(&counts[__ldg(ei + E + e)], 1);
    }
}

__global__ __launch_bounds__(256) void scanA_kernel(const int* __restrict__ counts,
                                                    int* __restrict__ bsum, int N)
{
    __shared__ int red[256];
    int tid = threadIdx.x;
    int base = blockIdx.x * 2048 + tid * 8;
    int s = 0;
    if (base < N) {
        int4 a = *reinterpret_cast<const int4*>(counts + base);
        int4 b = *reinterpret_cast<const int4*>(counts + base + 4);
        s = a.x + a.y + a.z + a.w + b.x + b.y + b.z + b.w;
    }
    red[tid] = s;
    __syncthreads();
    #pragma unroll
    for (int d = 128; d > 0; d >>= 1) {
        if (tid < d) red[tid] += red[tid + d];
        __syncthreads();
    }
    if (tid == 0) bsum[blockIdx.x] = red[0];
}

__global__ __launch_bounds__(64) void scanB_kernel(const int* __restrict__ bsum,
                                                   int* __restrict__ boff,
                                                   int* __restrict__ off, int B, int N)
{
    __shared__ int sh[64];
    int tid = threadIdx.x;
    int v = (tid < B) ? bsum[tid] : 0;
    sh[tid] = v;
    __syncthreads();
    #pragma unroll
    for (int d = 1; d < 64; d <<= 1) {
        int t = (tid >= d) ? sh[tid - d] : 0;
        __syncthreads();
        sh[tid] += t;
        __syncthreads();
    }
    boff[tid] = sh[tid] - v;
    if (tid == 63) off[N] = sh[63];
}

__global__ __launch_bounds__(256) void scanC_kernel(const int* __restrict__ counts,
                                                    const int* __restrict__ boff,
                                                    int* __restrict__ off,
                                                    int* __restrict__ cursor, int N)
{
    __shared__ int wsum[8], woff[8];
    int tid = threadIdx.x;
    int lane = tid & 31;
    int warp = tid >> 5;
    int base = blockIdx.x * 2048 + tid * 8;

    int4 a = make_int4(0, 0, 0, 0), b = make_int4(0, 0, 0, 0);
    if (base < N) {
        a = *reinterpret_cast<const int4*>(counts + base);
        b = *reinterpret_cast<const int4*>(counts + base + 4);
    }
    int s = a.x + a.y + a.z + a.w + b.x + b.y + b.z + b.w;

    int incl = s;
    #pragma unroll
    for (int d = 1; d < 32; d <<= 1) {
        int t = __shfl_up_sync(0xFFFFFFFFu, incl, d);
        if (lane >= d) incl += t;
    }
    if (lane == 31) wsum[warp] = incl;
    __syncthreads();
    if (tid == 0) {
        int run = 0;
        #pragma unroll
        for (int j = 0; j < 8; j++) { int t = wsum[j]; woff[j] = run; run += t; }
    }
    __syncthreads();

    int ex = __ldg(boff + blockIdx.x) + woff[warp] + (incl - s);
    if (base < N) {
        int o0 = ex;
        int o1 = o0 + a.x, o2 = o1 + a.y, o3 = o2 + a.z, o4 = o3 + a.w;
        int o5 = o4 + b.x, o6 = o5 + b.y, o7 = o6 + b.z;
        int4 oa = make_int4(o0, o1, o2, o3);
        int4 ob = make_int4(o4, o5, o6, o7);
        *reinterpret_cast<int4*>(off + base)        = oa;
        *reinterpret_cast<int4*>(off + base + 4)    = ob;
        *reinterpret_cast<int4*>(cursor + base)     = oa;
        *reinterpret_cast<int4*>(cursor + base + 4) = ob;
    }
}

__global__ void scatter_kernel(const int* __restrict__ ei, const float* __restrict__ ea,
                               int* __restrict__ cursor, int2* __restrict__ meta, int E)
{
    int i = blockIdx.x * blockDim.x + threadIdx.x;
    int base = i * 4;
    if (base >= E) return;
    if (((E & 3) == 0) && (base + 4 <= E)) {
        int4 s4 = *reinterpret_cast<const int4*>(ei + base);
        int4 d4 = *reinterpret_cast<const int4*>(ei + E + base);
        float4 e4 = *reinterpret_cast<const float4*>(ea + base);
        int p0 = atomicAdd(&cursor[d4.x], 1);
        int p1 = atomicAdd(&cursor[d4.y], 1);
        int p2 = atomicAdd(&cursor[d4.z], 1);
        int p3 = atomicAdd(&cursor[d4.w], 1);
        meta[p0] = make_int2(s4.x, __float_as_int(e4.x));
        meta[p1] = make_int2(s4.y, __float_as_int(e4.y));
        meta[p2] = make_int2(s4.z, __float_as_int(e4.z));
        meta[p3] = make_int2(s4.w, __float_as_int(e4.w));
    } else {
        int hi = min(base + 4, E);
        for (int e = base; e < hi; e++) {
            int s = __ldg(ei + e);
            int d = __ldg(ei + E + e);
            int pos = atomicAdd(&cursor[d], 1);
            meta[pos] = make_int2(s, __float_as_int(__ldg(ea + e)));
        }
    }
}

// =================================================================
// tf32 split + weight pre-split (unchanged)
// =================================================================
__device__ __forceinline__ void split_tf32(float v, uint32_t& hi, uint32_t& lo)
{
    asm("cvt.rna.tf32.f32 %0, %1;" : "=r"(hi) : "f"(v));
    float r = v - __uint_as_float(hi);
    asm("cvt.rna.tf32.f32 %0, %1;" : "=r"(lo) : "f"(r));
}

__global__ __launch_bounds__(256) void presplit_kernel(
    const float* __restrict__ m0, const float* __restrict__ m1, const float* __restrict__ m2,
    const float* __restrict__ m3, const float* __restrict__ m4, const float* __restrict__ m5,
    float* __restrict__ out)
{
    int idx = blockIdx.x * blockDim.x + threadIdx.x;
    if (idx >= 6 * 4096) return;
    int mat = idx >> 12;
    int j = idx & 4095;
    int k = j >> 6;
    int n = j & 63;

    const float* src;
    switch (mat) {
        case 0: src = m0; break; case 1: src = m1; break; case 2: src = m2; break;
        case 3: src = m3; break; case 4: src = m4; break; default: src = m5; break;
    }
    uint32_t hi, lo;
    split_tf32(__ldg(src + j), hi, lo);
    float* dst = out + (size_t)mat * 2 * WSEG_FLOATS;
    dst[n * APAD + k]               = __uint_as_float(hi);
    dst[WSEG_FLOATS + n * APAD + k] = __uint_as_float(lo);
}

// =================================================================
// x -> fp16 conversion (one-time)
// =================================================================
__global__ __launch_bounds__(256) void cvt_half_kernel(const float* __restrict__ X,
                                                       __half* __restrict__ Xh, int total)
{
    int i = blockIdx.x * blockDim.x + threadIdx.x;
    int base = i * 8;
    if (base >= total) return;
    float4 a = *reinterpret_cast<const float4*>(X + base);
    float4 b = *reinterpret_cast<const float4*>(X + base + 4);
    __half2 h[4];
    h[0] = __float22half2_rn(make_float2(a.x, a.y));
    h[1] = __float22half2_rn(make_float2(a.z, a.w));
    h[2] = __float22half2_rn(make_float2(b.x, b.y));
    h[3] = __float22half2_rn(make_float2(b.z, b.w));
    *reinterpret_cast<uint4*>(Xh + base) = *reinterpret_cast<uint4*>(h);
}

// =================================================================
// fp16-gather aggregation (R11 winner, byte-identical loop):
// warp per node, lane owns 2 channels, unroll-2
// =================================================================
__global__ __launch_bounds__(256) void aggx_h_kernel(const int* __restrict__ off,
                                                     const int2* __restrict__ meta,
                                                     const __half* __restrict__ Xh,
                                                     __half* __restrict__ XEh,
                                                     __half* __restrict__ X1h, int N)
{
    int w = (blockIdx.x * blockDim.x + threadIdx.x) >> 5;
    int lane = threadIdx.x & 31;
    if (w >= N) return;

    int beg = __ldg(off + w);
    int end = __ldg(off + w + 1);

    float2 aE = make_float2(0.f, 0.f);
    float2 a1 = make_float2(0.f, 0.f);

    const __half2* X2 = reinterpret_cast<const __half2*>(Xh);

    int k = beg;
    for (; k + 2 <= end; k += 2) {
        int2 m0 = __ldg(meta + k);
        int2 m1 = __ldg(meta + k + 1);
        float2 v0 = __half22float2(X2[(size_t)m0.x * 32 + lane]);
        float2 v1 = __half22float2(X2[(size_t)m1.x * 32 + lane]);
        float e0 = __int_as_float(m0.y);
        float e1 = __int_as_float(m1.y);
        aE.x = fmaf(e0, v0.x, aE.x); aE.y = fmaf(e0, v0.y, aE.y);
        aE.x = fmaf(e1, v1.x, aE.x); aE.y = fmaf(e1, v1.y, aE.y);
        a1.x += v0.x + v1.x;         a1.y += v0.y + v1.y;
    }
    if (k < end) {
        int2 m0 = __ldg(meta + k);
        float2 v0 = __half22float2(X2[(size_t)m0.x * 32 + lane]);
        float e0 = __int_as_float(m0.y);
        aE.x = fmaf(e0, v0.x, aE.x); aE.y = fmaf(e0, v0.y, aE.y);
        a1.x += v0.x;                a1.y += v0.y;
    }

    reinterpret_cast<__half2*>(XEh)[(size_t)w * 32 + lane] = __float22half2_rn(aE);
    reinterpret_cast<__half2*>(X1h)[(size_t)w * 32 + lane] = __float22half2_rn(a1);
}

// =================================================================
// TF32 tensor-core GEMM (unchanged from R11 winner)
// =================================================================
#define SA_FLOATS (128 * APAD)     /* 8704 */
#define TC_SMEM_FLOATS (SA_FLOATS + 2 * WSEG_FLOATS)
#define TC_SMEM_BYTES  (TC_SMEM_FLOATS * 4)   /* 69632 B */

__device__ __forceinline__ void mma_tf32(float* c, const uint32_t* a, const uint32_t* b)
{
    asm("mma.sync.aligned.m16n8k8.row.col.f32.tf32.tf32.f32 "
        "{%0,%1,%2,%3}, {%4,%5,%6,%7}, {%8,%9}, {%0,%1,%2,%3};"
        : "+f"(c[0]), "+f"(c[1]), "+f"(c[2]), "+f"(c[3])
        : "r"(a[0]), "r"(a[1]), "r"(a[2]), "r"(a[3]), "r"(b[0]), "r"(b[1]));
}

__global__ __launch_bounds__(256, 3) void gemm192_tc(const __half* __restrict__ XEh,
                                                     const __half* __restrict__ X1h,
                                                     const __half* __restrict__ Xh,
                                                     const float* __restrict__ Wsp,
                                                     const float* __restrict__ bias,
                                                     __half* __restrict__ Hh, int N)
{
    extern __shared__ float sm[];
    float* sA   = sm;
    float* sWhi = sm + SA_FLOATS;
    float* sWlo = sWhi + WSEG_FLOATS;

    const int tid  = threadIdx.x;
    const int lane = tid & 31;
    const int wid  = tid >> 5;
    const int grp  = lane >> 2;
    const int qid  = lane & 3;
    const int wm   = wid & 3;
    const int wn   = wid >> 2;
    const int row0 = blockIdx.x * 128;

    float c[2][4][4];
    #pragma unroll
    for (int mt = 0; mt < 2; mt++)
        #pragma unroll
        for (int nt = 0; nt < 4; nt++)
            #pragma unroll
            for (int j = 0; j < 4; j++) c[mt][nt][j] = 0.f;

    #pragma unroll
    for (int seg = 0; seg < 3; seg++) {
        const __half* A = (seg == 0) ? XEh : (seg == 1) ? X1h : Xh;
        const float* Wseg = Wsp + (size_t)seg * 2 * WSEG_FLOATS;

        if (seg > 0) __syncthreads();

        #pragma unroll
        for (int i = tid; i < 2048; i += 256) {
            int r  = i >> 4;
            int k4 = (i & 15) * 4;
            int row = row0 + r;
            float4 v = make_float4(0.f, 0.f, 0.f, 0.f);
            if (row < N) {
                uint2 hv = *reinterpret_cast<const uint2*>(A + (size_t)row * 64 + k4);
                float2 lo2 = __half22float2(*reinterpret_cast<__half2*>(&hv.x));
                float2 hi2 = __half22float2(*reinterpret_cast<__half2*>(&hv.y));
                v = make_float4(lo2.x, lo2.y, hi2.x, hi2.y);
            }
            *reinterpret_cast<float4*>(&sA[r * APAD + k4]) = v;
        }
        #pragma unroll
        for (int i = tid; i < 2176; i += 256) {
            float4 v = __ldg(reinterpret_cast<const float4*>(Wseg) + i);
            *reinterpret_cast<float4*>(&sWhi[i * 4]) = v;
        }
        __syncthreads();

        #pragma unroll
        for (int kst = 0; kst < 8; kst++) {
            const int k0 = kst * 8;

            uint32_t a[2][4];
            #pragma unroll
            for (int mt = 0; mt < 2; mt++) {
                int r0 = (wm * 32 + mt * 16 + grp) * APAD + k0 + qid;
                int r1 = r0 + 8 * APAD;
                a[mt][0] = __float_as_uint(sA[r0]);
                a[mt][1] = __float_as_uint(sA[r1]);
                a[mt][2] = __float_as_uint(sA[r0 + 4]);
                a[mt][3] = __float_as_uint(sA[r1 + 4]);
            }
            uint32_t bhi[4][2], blo[4][2];
            #pragma unroll
            for (int nt = 0; nt < 4; nt++) {
                int b0 = (wn * 32 + nt * 8 + grp) * APAD + k0 + qid;
                bhi[nt][0] = __float_as_uint(sWhi[b0]);
                bhi[nt][1] = __float_as_uint(sWhi[b0 + 4]);
                blo[nt][0] = __float_as_uint(sWlo[b0]);
                blo[nt][1] = __float_as_uint(sWlo[b0 + 4]);
            }

            #pragma unroll
            for (int mt = 0; mt < 2; mt++) {
                #pragma unroll
                for (int nt = 0; nt < 4; nt++) {
                    mma_tf32(c[mt][nt], a[mt], bhi[nt]);
                    mma_tf32(c[mt][nt], a[mt], blo[nt]);
                }
            }
        }
    }

    #pragma unroll
    for (int mt = 0; mt < 2; mt++) {
        int rbase = row0 + wm * 32 + mt * 16 + grp;
        #pragma unroll
        for (int nt = 0; nt < 4; nt++) {
            int col = wn * 32 + nt * 8 + 2 * qid;
            float2 b2 = __ldg(reinterpret_cast<const float2*>(bias + col));
            if (rbase < N) {
                float2 v = make_float2(fmaxf(c[mt][nt][0] + b2.x, 0.f),
                                       fmaxf(c[mt][nt][1] + b2.y, 0.f));
                *reinterpret_cast<__half2*>(Hh + (size_t)rbase * 64 + col) = __float22half2_rn(v);
            }
            if (rbase + 8 < N) {
                float2 v = make_float2(fmaxf(c[mt][nt][2] + b2.x, 0.f),
                                       fmaxf(c[mt][nt][3] + b2.y, 0.f));
                *reinterpret_cast<__half2*>(Hh + (size_t)(rbase + 8) * 64 + col) = __float22half2_rn(v);
            }
        }
    }
}

// =================================================================
// Layer 3 project-first: PQ3[row]=HB@Wm3 | HB@Bm3 (fp32),
// OUT[row]=HB@Wr3+b3. One thread per node row.
// =================================================================
__global__ __launch_bounds__(256) void gemm3_pq(const __half* __restrict__ HBh,
                                                const float* __restrict__ Wm,
                                                const float* __restrict__ Bm,
                                                const float* __restrict__ Wr,
                                                const float* __restrict__ b,
                                                float* __restrict__ PQ3,
                                                float* __restrict__ OUT, int N)
{
    __shared__ float sw[768];   // [0:256) Wm, [256:512) Bm, [512:768) Wr  layout k*4+c
    int tid = threadIdx.x;
    if (tid < 256) { sw[tid] = Wm[tid]; sw[256 + tid] = Bm[tid]; sw[512 + tid] = Wr[tid]; }
    __syncthreads();

    int row = blockIdx.x * blockDim.x + tid;
    if (row >= N) return;

    float p[4] = {0,0,0,0}, q[4] = {0,0,0,0}, r[4] = {0,0,0,0};
    const uint4* hb4 = reinterpret_cast<const uint4*>(HBh + (size_t)row * 64);

    #pragma unroll
    for (int blk = 0; blk < 8; blk++) {       // 8 halves per uint4
        uint4 hv = __ldg(hb4 + blk);
        float2 f0 = __half22float2(*reinterpret_cast<__half2*>(&hv.x));
        float2 f1 = __half22float2(*reinterpret_cast<__half2*>(&hv.y));
        float2 f2 = __half22float2(*reinterpret_cast<__half2*>(&hv.z));
        float2 f3 = __half22float2(*reinterpret_cast<__half2*>(&hv.w));
        float xs[8] = {f0.x, f0.y, f1.x, f1.y, f2.x, f2.y, f3.x, f3.y};
        #pragma unroll
        for (int j = 0; j < 8; j++) {
            int k = blk * 8 + j;
            #pragma unroll
            for (int c = 0; c < 4; c++) {
                p[c] = fmaf(xs[j], sw[k * 4 + c], p[c]);
                q[c] = fmaf(xs[j], sw[256 + k * 4 + c], q[c]);
                r[c] = fmaf(xs[j], sw[512 + k * 4 + c], r[c]);
            }
        }
    }

    float4* pq = reinterpret_cast<float4*>(PQ3 + (size_t)row * 8);
    pq[0] = make_float4(p[0], p[1], p[2], p[3]);
    pq[1] = make_float4(q[0], q[1], q[2], q[3]);
    float4 o;
    o.x = r[0] + __ldg(b + 0);
    o.y = r[1] + __ldg(b + 1);
    o.z = r[2] + __ldg(b + 2);
    o.w = r[3] + __ldg(b + 3);
    *reinterpret_cast<float4*>(OUT + (size_t)row * 4) = o;
}

// =================================================================
// Layer 3 aggregate + log_softmax: thread per node, 32B/edge gather.
// out = logsm(OUT_base + sum_e (e*P3[s] + Q3[s]))
// =================================================================
__global__ __launch_bounds__(256) void agg3_ls(const int* __restrict__ off,
                                               const int2* __restrict__ meta,
                                               const float* __restrict__ PQ3,
                                               float* __restrict__ OUT, int N)
{
    int w = blockIdx.x * blockDim.x + threadIdx.x;
    if (w >= N) return;

    int beg = __ldg(off + w);
    int end = __ldg(off + w + 1);

    float acc[4] = {0.f, 0.f, 0.f, 0.f};

    int k = beg;
    for (; k + 2 <= end; k += 2) {
        int2 m0 = __ldg(meta + k);
        int2 m1 = __ldg(meta + k + 1);
        const float4* pq0 = reinterpret_cast<const float4*>(PQ3 + (size_t)m0.x * 8);
        const float4* pq1 = reinterpret_cast<const float4*>(PQ3 + (size_t)m1.x * 8);
        float4 p0 = __ldg(pq0);
        float4 q0 = __ldg(pq0 + 1);
        float4 p1 = __ldg(pq1);
        float4 q1 = __ldg(pq1 + 1);
        float e0 = __int_as_float(m0.y);
        float e1 = __int_as_float(m1.y);
        acc[0] += fmaf(e0, p0.x, q0.x) + fmaf(e1, p1.x, q1.x);
        acc[1] += fmaf(e0, p0.y, q0.y) + fmaf(e1, p1.y, q1.y);
        acc[2] += fmaf(e0, p0.z, q0.z) + fmaf(e1, p1.z, q1.z);
        acc[3] += fmaf(e0, p0.w, q0.w) + fmaf(e1, p1.w, q1.w);
    }
    if (k < end) {
        int2 m0 = __ldg(meta + k);
        const float4* pq0 = reinterpret_cast<const float4*>(PQ3 + (size_t)m0.x * 8);
        float4 p0 = __ldg(pq0);
        float4 q0 = __ldg(pq0 + 1);
        float e0 = __int_as_float(m0.y);
        acc[0] += fmaf(e0, p0.x, q0.x);
        acc[1] += fmaf(e0, p0.y, q0.y);
        acc[2] += fmaf(e0, p0.z, q0.z);
        acc[3] += fmaf(e0, p0.w, q0.w);
    }

    float4 base = *reinterpret_cast<float4*>(OUT + (size_t)w * 4);
    float v0 = base.x + acc[0];
    float v1 = base.y + acc[1];
    float v2 = base.z + acc[2];
    float v3 = base.w + acc[3];

    float m = fmaxf(fmaxf(v0, v1), fmaxf(v2, v3));
    float s = __expf(v0 - m) + __expf(v1 - m) + __expf(v2 - m) + __expf(v3 - m);
    float lse = m + __logf(s);

    float4 o;
    o.x = v0 - lse; o.y = v1 - lse; o.z = v2 - lse; o.w = v3 - lse;
    *reinterpret_cast<float4*>(OUT + (size_t)w * 4) = o;
}

// =================================================================
extern "C" void kernel_launch(void* const* d_in, const int* in_sizes, int n_in,
                              void* d_out, int out_size)
{
    const float* x   = (const float*)d_in[0];
    const int*   ei  = (const int*)  d_in[1];
    const float* ea  = (const float*)d_in[2];
    const float* We1 = (const float*)d_in[3];
    const float* be1 = (const float*)d_in[4];
    const float* Wr1 = (const float*)d_in[5];
    const float* b1  = (const float*)d_in[6];
    const float* We2 = (const float*)d_in[7];
    const float* be2 = (const float*)d_in[8];
    const float* Wr2 = (const float*)d_in[9];
    const float* b2  = (const float*)d_in[10];
    const float* We3 = (const float*)d_in[11];
    const float* be3 = (const float*)d_in[12];
    const float* Wr3 = (const float*)d_in[13];
    const float* b3  = (const float*)d_in[14];

    const int N = in_sizes[0] / DIN;
    const int E = in_sizes[2];

    float *Wsp, *PQ3, *OUT = (float*)d_out;
    __half *XEh, *X1h, *Xh, *HAh, *HBh;
    int *counts, *off, *cursor, *bsum, *boff;
    int2 *meta;
    cudaGetSymbolAddress((void**)&XEh, g_XEh);
    cudaGetSymbolAddress((void**)&X1h, g_X1h);
    cudaGetSymbolAddress((void**)&Xh, g_Xh);
    cudaGetSymbolAddress((void**)&HAh, g_HAh);
    cudaGetSymbolAddress((void**)&HBh, g_HBh);
    cudaGetSymbolAddress((void**)&PQ3, g_PQ3);
    cudaGetSymbolAddress((void**)&Wsp, g_Wsp);
    cudaGetSymbolAddress((void**)&counts, g_counts);
    cudaGetSymbolAddress((void**)&off, g_off);
    cudaGetSymbolAddress((void**)&cursor, g_cursor);
    cudaGetSymbolAddress((void**)&bsum, g_bsum);
    cudaGetSymbolAddress((void**)&boff, g_boff);
    cudaGetSymbolAddress((void**)&meta, g_meta);

    cudaFuncSetAttribute(gemm192_tc, cudaFuncAttributeMaxDynamicSharedMemorySize, TC_SMEM_BYTES);

    const int edge4Grid = (E / 4 + 256) / 256;
    const int rowGrid   = (N + 255) / 256;
    const int aggGrid   = (N * 32 + 255) / 256;
    const int tcGrid    = (N + 127) / 128;
    const int scanGrid  = (N + 2047) / 2048;
    const int cvtGrid   = (N * 64 / 8 + 255) / 256;

    // ---- CSR build + weight pre-split (layers 1-2 only) + x->fp16 ----
    zero_kernel<<<rowGrid, 256>>>(counts, N);
    hist_kernel<<<edge4Grid, 256>>>(ei, counts, E);
    scanA_kernel<<<scanGrid, 256>>>(counts, bsum, N);
    scanB_kernel<<<1, 64>>>(bsum, boff, off, scanGrid, N);
    scanC_kernel<<<scanGrid, 256>>>(counts, boff, off, cursor, N);
    scatter_kernel<<<edge4Grid, 256>>>(ei, ea, cursor, meta, E);
    presplit_kernel<<<96, 256>>>(We1, be1, Wr1, We2, be2, Wr2, Wsp);
    cvt_half_kernel<<<cvtGrid, 256>>>(x, Xh, N * 64);

    // ---- layer 1 ----
    aggx_h_kernel<<<aggGrid, 256>>>(off, meta, Xh, XEh, X1h, N);
    gemm192_tc<<<tcGrid, 256, TC_SMEM_BYTES>>>(XEh, X1h, Xh, Wsp, b1, HAh, N);

    // ---- layer 2 ----
    aggx_h_kernel<<<aggGrid, 256>>>(off, meta, HAh, XEh, X1h, N);
    gemm192_tc<<<tcGrid, 256, TC_SMEM_BYTES>>>(XEh, X1h, HAh,
                                               Wsp + (size_t)3 * 2 * WSEG_FLOATS, b2, HBh, N);

    // ---- layer 3: project-first (64->4), then 32B/edge aggregate ----
    gemm3_pq<<<rowGrid, 256>>>(HBh, We3, be3, Wr3, b3, PQ3, OUT, N);
    agg3_ls<<<rowGrid, 256>>>(off, meta, PQ3, OUT, N);
}

// round 16
// speedup vs baseline: 1.4310x; 1.2446x over previous
#include <cuda_runtime.h>
#include <cuda_fp16.h>
#include <cstdint>

#define MAXN 100000
#define MAXE 1600000
#define DIN  64

// ---------------- scratch (no cudaMalloc allowed) ----------------
__device__ __half g_XEh[(size_t)MAXN * 64];  // sum of e * X[src] per dst (fp16)
__device__ __half g_X1h[(size_t)MAXN * 64];  // sum of X[src] per dst (fp16)
__device__ __half g_Xh[(size_t)MAXN * 64];   // fp16 copy of input x
__device__ __half g_HAh[(size_t)MAXN * 64];  // relu(layer1 out), fp16
__device__ __half g_HBh[(size_t)MAXN * 64];  // relu(layer2 out), fp16
__device__ float  g_PQ3[(size_t)MAXN * 8];   // layer3 P|Q per node (fp32)
__device__ int    g_counts[MAXN];
__device__ int    g_off[MAXN + 1];
__device__ int    g_cursor[MAXN];
__device__ int    g_bsum[64];
__device__ int    g_boff[64];
__device__ int2   g_meta[MAXE];              // {src, bits(e)} grouped by dst

// pre-transposed fp16 weights for layers 1-2: [mat 0..5][n*HPAD + k]
#define HPAD 72
#define SWH  (64 * HPAD)                      /* 4608 halves per mat */
__device__ __half g_Wh[6 * SWH];

// =================================================================
// CSR build (R15 winner, unchanged)
// =================================================================
__global__ void zero_kernel(int* __restrict__ counts, int N)
{
    int i = blockIdx.x * blockDim.x + threadIdx.x;
    if (i < N) counts[i] = 0;
}

__global__ void hist_kernel(const int* __restrict__ ei, int* __restrict__ counts, int E)
{
    int i = blockIdx.x * blockDim.x + threadIdx.x;
    int base = i * 4;
    if (base >= E) return;
    if (((E & 3) == 0) && (base + 4 <= E)) {
        int4 d = *reinterpret_cast<const int4*>(ei + E + base);
        atomicAdd(&counts[d.x], 1);
        atomicAdd(&counts[d.y], 1);
        atomicAdd(&counts[d.z], 1);
        atomicAdd(&counts[d.w], 1);
    } else {
        int hi = min(base + 4, E);
        for (int e = base; e < hi; e++) atomicAdd(&counts[__ldg(ei + E + e)], 1);
    }
}

__global__ __launch_bounds__(256) void scanA_kernel(const int* __restrict__ counts,
                                                    int* __restrict__ bsum, int N)
{
    __shared__ int red[256];
    int tid = threadIdx.x;
    int base = blockIdx.x * 2048 + tid * 8;
    int s = 0;
    if (base < N) {
        int4 a = *reinterpret_cast<const int4*>(counts + base);
        int4 b = *reinterpret_cast<const int4*>(counts + base + 4);
        s = a.x + a.y + a.z + a.w + b.x + b.y + b.z + b.w;
    }
    red[tid] = s;
    __syncthreads();
    #pragma unroll
    for (int d = 128; d > 0; d >>= 1) {
        if (tid < d) red[tid] += red[tid + d];
        __syncthreads();
    }
    if (tid == 0) bsum[blockIdx.x] = red[0];
}

__global__ __launch_bounds__(64) void scanB_kernel(const int* __restrict__ bsum,
                                                   int* __restrict__ boff,
                                                   int* __restrict__ off, int B, int N)
{
    __shared__ int sh[64];
    int tid = threadIdx.x;
    int v = (tid < B) ? bsum[tid] : 0;
    sh[tid] = v;
    __syncthreads();
    #pragma unroll
    for (int d = 1; d < 64; d <<= 1) {
        int t = (tid >= d) ? sh[tid - d] : 0;
        __syncthreads();
        sh[tid] += t;
        __syncthreads();
    }
    boff[tid] = sh[tid] - v;
    if (tid == 63) off[N] = sh[63];
}

__global__ __launch_bounds__(256) void scanC_kernel(const int* __restrict__ counts,
                                                    const int* __restrict__ boff,
                                                    int* __restrict__ off,
                                                    int* __restrict__ cursor, int N)
{
    __shared__ int wsum[8], woff[8];
    int tid = threadIdx.x;
    int lane = tid & 31;
    int warp = tid >> 5;
    int base = blockIdx.x * 2048 + tid * 8;

    int4 a = make_int4(0, 0, 0, 0), b = make_int4(0, 0, 0, 0);
    if (base < N) {
        a = *reinterpret_cast<const int4*>(counts + base);
        b = *reinterpret_cast<const int4*>(counts + base + 4);
    }
    int s = a.x + a.y + a.z + a.w + b.x + b.y + b.z + b.w;

    int incl = s;
    #pragma unroll
    for (int d = 1; d < 32; d <<= 1) {
        int t = __shfl_up_sync(0xFFFFFFFFu, incl, d);
        if (lane >= d) incl += t;
    }
    if (lane == 31) wsum[warp] = incl;
    __syncthreads();
    if (tid == 0) {
        int run = 0;
        #pragma unroll
        for (int j = 0; j < 8; j++) { int t = wsum[j]; woff[j] = run; run += t; }
    }
    __syncthreads();

    int ex = __ldg(boff + blockIdx.x) + woff[warp] + (incl - s);
    if (base < N) {
        int o0 = ex;
        int o1 = o0 + a.x, o2 = o1 + a.y, o3 = o2 + a.z, o4 = o3 + a.w;
        int o5 = o4 + b.x, o6 = o5 + b.y, o7 = o6 + b.z;
        int4 oa = make_int4(o0, o1, o2, o3);
        int4 ob = make_int4(o4, o5, o6, o7);
        *reinterpret_cast<int4*>(off + base)        = oa;
        *reinterpret_cast<int4*>(off + base + 4)    = ob;
        *reinterpret_cast<int4*>(cursor + base)     = oa;
        *reinterpret_cast<int4*>(cursor + base + 4) = ob;
    }
}

__global__ void scatter_kernel(const int* __restrict__ ei, const float* __restrict__ ea,
                               int* __restrict__ cursor, int2* __restrict__ meta, int E)
{
    int i = blockIdx.x * blockDim.x + threadIdx.x;
    int base = i * 4;
    if (base >= E) return;
    if (((E & 3) == 0) && (base + 4 <= E)) {
        int4 s4 = *reinterpret_cast<const int4*>(ei + base);
        int4 d4 = *reinterpret_cast<const int4*>(ei + E + base);
        float4 e4 = *reinterpret_cast<const float4*>(ea + base);
        int p0 = atomicAdd(&cursor[d4.x], 1);
        int p1 = atomicAdd(&cursor[d4.y], 1);
        int p2 = atomicAdd(&cursor[d4.z], 1);
        int p3 = atomicAdd(&cursor[d4.w], 1);
        meta[p0] = make_int2(s4.x, __float_as_int(e4.x));
        meta[p1] = make_int2(s4.y, __float_as_int(e4.y));
        meta[p2] = make_int2(s4.z, __float_as_int(e4.z));
        meta[p3] = make_int2(s4.w, __float_as_int(e4.w));
    } else {
        int hi = min(base + 4, E);
        for (int e = base; e < hi; e++) {
            int s = __ldg(ei + e);
            int d = __ldg(ei + E + e);
            int pos = atomicAdd(&cursor[d], 1);
            meta[pos] = make_int2(s, __float_as_int(__ldg(ea + e)));
        }
    }
}

// =================================================================
// Weight pre-transpose to fp16: Wh[mat][n*HPAD+k] = (half)W[k*64+n]
// =================================================================
__global__ __launch_bounds__(256) void pretrans_h_kernel(
    const float* __restrict__ m0, const float* __restrict__ m1, const float* __restrict__ m2,
    const float* __restrict__ m3, const float* __restrict__ m4, const float* __restrict__ m5,
    __half* __restrict__ out)
{
    int idx = blockIdx.x * blockDim.x + threadIdx.x;
    if (idx >= 6 * 4096) return;
    int mat = idx >> 12;
    int j = idx & 4095;
    int k = j >> 6;
    int n = j & 63;

    const float* src;
    switch (mat) {
        case 0: src = m0; break; case 1: src = m1; break; case 2: src = m2; break;
        case 3: src = m3; break; case 4: src = m4; break; default: src = m5; break;
    }
    out[(size_t)mat * SWH + n * HPAD + k] = __float2half_rn(__ldg(src + j));
}

// =================================================================
// x -> fp16 conversion (one-time)
// =================================================================
__global__ __launch_bounds__(256) void cvt_half_kernel(const float* __restrict__ X,
                                                       __half* __restrict__ Xh, int total)
{
    int i = blockIdx.x * blockDim.x + threadIdx.x;
    int base = i * 8;
    if (base >= total) return;
    float4 a = *reinterpret_cast<const float4*>(X + base);
    float4 b = *reinterpret_cast<const float4*>(X + base + 4);
    __half2 h[4];
    h[0] = __float22half2_rn(make_float2(a.x, a.y));
    h[1] = __float22half2_rn(make_float2(a.z, a.w));
    h[2] = __float22half2_rn(make_float2(b.x, b.y));
    h[3] = __float22half2_rn(make_float2(b.z, b.w));
    *reinterpret_cast<uint4*>(Xh + base) = *reinterpret_cast<uint4*>(h);
}

// =================================================================
// fp16-gather aggregation (R11/R15 winner, byte-identical loop)
// =================================================================
__global__ __launch_bounds__(256) void aggx_h_kernel(const int* __restrict__ off,
                                                     const int2* __restrict__ meta,
                                                     const __half* __restrict__ Xh,
                                                     __half* __restrict__ XEh,
                                                     __half* __restrict__ X1h, int N)
{
    int w = (blockIdx.x * blockDim.x + threadIdx.x) >> 5;
    int lane = threadIdx.x & 31;
    if (w >= N) return;

    int beg = __ldg(off + w);
    int end = __ldg(off + w + 1);

    float2 aE = make_float2(0.f, 0.f);
    float2 a1 = make_float2(0.f, 0.f);

    const __half2* X2 = reinterpret_cast<const __half2*>(Xh);

    int k = beg;
    for (; k + 2 <= end; k += 2) {
        int2 m0 = __ldg(meta + k);
        int2 m1 = __ldg(meta + k + 1);
        float2 v0 = __half22float2(X2[(size_t)m0.x * 32 + lane]);
        float2 v1 = __half22float2(X2[(size_t)m1.x * 32 + lane]);
        float e0 = __int_as_float(m0.y);
        float e1 = __int_as_float(m1.y);
        aE.x = fmaf(e0, v0.x, aE.x); aE.y = fmaf(e0, v0.y, aE.y);
        aE.x = fmaf(e1, v1.x, aE.x); aE.y = fmaf(e1, v1.y, aE.y);
        a1.x += v0.x + v1.x;         a1.y += v0.y + v1.y;
    }
    if (k < end) {
        int2 m0 = __ldg(meta + k);
        float2 v0 = __half22float2(X2[(size_t)m0.x * 32 + lane]);
        float e0 = __int_as_float(m0.y);
        aE.x = fmaf(e0, v0.x, aE.x); aE.y = fmaf(e0, v0.y, aE.y);
        a1.x += v0.x;                a1.y += v0.y;
    }

    reinterpret_cast<__half2*>(XEh)[(size_t)w * 32 + lane] = __float22half2_rn(aE);
    reinterpret_cast<__half2*>(X1h)[(size_t)w * 32 + lane] = __float22half2_rn(a1);
}

// =================================================================
// fp16 HMMA GEMM: H = relu(XE@Wm + X1@Bm + X@Wr + b)
// mma.m16n8k16.f32.f16.f16.f32; all operands fp16, fp32 accum.
// CTA 128 rows x 64 cols, 8 warps (32x32 warp tiles).
// smem: A[128][72] + W[64][72] halves = 27648 B (high occupancy).
// =================================================================
#define SAH (128 * HPAD)                      /* 9216 halves */
#define F16_SMEM_BYTES ((SAH + SWH) * 2)      /* 27648 B */

__device__ __forceinline__ void mma_f16(float* c, const uint32_t* a, const uint32_t* b)
{
    asm("mma.sync.aligned.m16n8k16.row.col.f32.f16.f16.f32 "
        "{%0,%1,%2,%3}, {%4,%5,%6,%7}, {%8,%9}, {%0,%1,%2,%3};"
        : "+f"(c[0]), "+f"(c[1]), "+f"(c[2]), "+f"(c[3])
        : "r"(a[0]), "r"(a[1]), "r"(a[2]), "r"(a[3]), "r"(b[0]), "r"(b[1]));
}

__global__ __launch_bounds__(256) void gemm192_f16(const __half* __restrict__ XEh,
                                                   const __half* __restrict__ X1h,
                                                   const __half* __restrict__ Xh,
                                                   const __half* __restrict__ Wh,
                                                   const float* __restrict__ bias,
                                                   __half* __restrict__ Hh, int N)
{
    extern __shared__ __half smh[];
    __half* sA = smh;                  // [row*HPAD + k]
    __half* sW = smh + SAH;            // [n*HPAD + k]

    const int tid  = threadIdx.x;
    const int lane = tid & 31;
    const int wid  = tid >> 5;
    const int grp  = lane >> 2;        // 0..7
    const int qid  = lane & 3;         // 0..3
    const int wm   = wid & 3;          // warp row 0..3
    const int wn   = wid >> 2;         // warp col 0..1
    const int row0 = blockIdx.x * 128;

    float c[2][4][4];
    #pragma unroll
    for (int mt = 0; mt < 2; mt++)
        #pragma unroll
        for (int nt = 0; nt < 4; nt++)
            #pragma unroll
            for (int j = 0; j < 4; j++) c[mt][nt][j] = 0.f;

    #pragma unroll
    for (int seg = 0; seg < 3; seg++) {
        const __half* A = (seg == 0) ? XEh : (seg == 1) ? X1h : Xh;
        const __half* Wseg = Wh + (size_t)seg * SWH;

        if (seg > 0) __syncthreads();

        // stage A tile: raw fp16 copy, 1024 uint4 (8 halves each)
        #pragma unroll
        for (int i = tid; i < 1024; i += 256) {
            int r  = i >> 3;
            int k8 = (i & 7) * 8;
            int row = row0 + r;
            uint4 v = make_uint4(0u, 0u, 0u, 0u);
            if (row < N) v = *reinterpret_cast<const uint4*>(A + (size_t)row * 64 + k8);
            *reinterpret_cast<uint4*>(sA + r * HPAD + k8) = v;
        }
        // stage W (pre-transposed, pre-padded): 576 uint4 linear copy
        for (int i = tid; i < 576; i += 256) {
            uint4 v = __ldg(reinterpret_cast<const uint4*>(Wseg) + i);
            *reinterpret_cast<uint4*>(sW + i * 8) = v;
        }
        __syncthreads();

        #pragma unroll
        for (int kst = 0; kst < 4; kst++) {
            const int k0 = kst * 16;

            uint32_t a[2][4];
            #pragma unroll
            for (int mt = 0; mt < 2; mt++) {
                const __half* pa = sA + (wm * 32 + mt * 16 + grp) * HPAD + k0 + 2 * qid;
                a[mt][0] = *reinterpret_cast<const uint32_t*>(pa);
                a[mt][1] = *reinterpret_cast<const uint32_t*>(pa + 8 * HPAD);
                a[mt][2] = *reinterpret_cast<const uint32_t*>(pa + 8);
                a[mt][3] = *reinterpret_cast<const uint32_t*>(pa + 8 * HPAD + 8);
            }
            uint32_t b[4][2];
            #pragma unroll
            for (int nt = 0; nt < 4; nt++) {
                const __half* pb = sW + (wn * 32 + nt * 8 + grp) * HPAD + k0 + 2 * qid;
                b[nt][0] = *reinterpret_cast<const uint32_t*>(pb);
                b[nt][1] = *reinterpret_cast<const uint32_t*>(pb + 8);
            }

            #pragma unroll
            for (int mt = 0; mt < 2; mt++)
                #pragma unroll
                for (int nt = 0; nt < 4; nt++)
                    mma_f16(c[mt][nt], a[mt], b[nt]);
        }
    }

    // epilogue: bias + relu + fp16 store (same fragment layout as tf32 path)
    #pragma unroll
    for (int mt = 0; mt < 2; mt++) {
        int rbase = row0 + wm * 32 + mt * 16 + grp;
        #pragma unroll
        for (int nt = 0; nt < 4; nt++) {
            int col = wn * 32 + nt * 8 + 2 * qid;
            float2 b2 = __ldg(reinterpret_cast<const float2*>(bias + col));
            if (rbase < N) {
                float2 v = make_float2(fmaxf(c[mt][nt][0] + b2.x, 0.f),
                                       fmaxf(c[mt][nt][1] + b2.y, 0.f));
                *reinterpret_cast<__half2*>(Hh + (size_t)rbase * 64 + col) = __float22half2_rn(v);
            }
            if (rbase + 8 < N) {
                float2 v = make_float2(fmaxf(c[mt][nt][2] + b2.x, 0.f),
                                       fmaxf(c[mt][nt][3] + b2.y, 0.f));
                *reinterpret_cast<__half2*>(Hh + (size_t)(rbase + 8) * 64 + col) = __float22half2_rn(v);
            }
        }
    }
}

// =================================================================
// Layer 3 project-first (R15 winner, unchanged):
// PQ3[row]=HB@Wm3 | HB@Bm3 (fp32); OUT[row]=HB@Wr3+b3
// =================================================================
__global__ __launch_bounds__(256) void gemm3_pq(const __half* __restrict__ HBh,
                                                const float* __restrict__ Wm,
                                                const float* __restrict__ Bm,
                                                const float* __restrict__ Wr,
                                                const float* __restrict__ b,
                                                float* __restrict__ PQ3,
                                                float* __restrict__ OUT, int N)
{
    __shared__ float sw[768];
    int tid = threadIdx.x;
    if (tid < 256) { sw[tid] = Wm[tid]; sw[256 + tid] = Bm[tid]; sw[512 + tid] = Wr[tid]; }
    __syncthreads();

    int row = blockIdx.x * blockDim.x + tid;
    if (row >= N) return;

    float p[4] = {0,0,0,0}, q[4] = {0,0,0,0}, r[4] = {0,0,0,0};
    const uint4* hb4 = reinterpret_cast<const uint4*>(HBh + (size_t)row * 64);

    #pragma unroll
    for (int blk = 0; blk < 8; blk++) {
        uint4 hv = __ldg(hb4 + blk);
        float2 f0 = __half22float2(*reinterpret_cast<__half2*>(&hv.x));
        float2 f1 = __half22float2(*reinterpret_cast<__half2*>(&hv.y));
        float2 f2 = __half22float2(*reinterpret_cast<__half2*>(&hv.z));
        float2 f3 = __half22float2(*reinterpret_cast<__half2*>(&hv.w));
        float xs[8] = {f0.x, f0.y, f1.x, f1.y, f2.x, f2.y, f3.x, f3.y};
        #pragma unroll
        for (int j = 0; j < 8; j++) {
            int k = blk * 8 + j;
            #pragma unroll
            for (int c = 0; c < 4; c++) {
                p[c] = fmaf(xs[j], sw[k * 4 + c], p[c]);
                q[c] = fmaf(xs[j], sw[256 + k * 4 + c], q[c]);
                r[c] = fmaf(xs[j], sw[512 + k * 4 + c], r[c]);
            }
        }
    }

    float4* pq = reinterpret_cast<float4*>(PQ3 + (size_t)row * 8);
    pq[0] = make_float4(p[0], p[1], p[2], p[3]);
    pq[1] = make_float4(q[0], q[1], q[2], q[3]);
    float4 o;
    o.x = r[0] + __ldg(b + 0);
    o.y = r[1] + __ldg(b + 1);
    o.z = r[2] + __ldg(b + 2);
    o.w = r[3] + __ldg(b + 3);
    *reinterpret_cast<float4*>(OUT + (size_t)row * 4) = o;
}

// =================================================================
// Layer 3 aggregate + log_softmax (R15 winner, unchanged)
// =================================================================
__global__ __launch_bounds__(256) void agg3_ls(const int* __restrict__ off,
                                               const int2* __restrict__ meta,
                                               const float* __restrict__ PQ3,
                                               float* __restrict__ OUT, int N)
{
    int w = blockIdx.x * blockDim.x + threadIdx.x;
    if (w >= N) return;

    int beg = __ldg(off + w);
    int end = __ldg(off + w + 1);

    float acc[4] = {0.f, 0.f, 0.f, 0.f};

    int k = beg;
    for (; k + 2 <= end; k += 2) {
        int2 m0 = __ldg(meta + k);
        int2 m1 = __ldg(meta + k + 1);
        const float4* pq0 = reinterpret_cast<const float4*>(PQ3 + (size_t)m0.x * 8);
        const float4* pq1 = reinterpret_cast<const float4*>(PQ3 + (size_t)m1.x * 8);
        float4 p0 = __ldg(pq0);
        float4 q0 = __ldg(pq0 + 1);
        float4 p1 = __ldg(pq1);
        float4 q1 = __ldg(pq1 + 1);
        float e0 = __int_as_float(m0.y);
        float e1 = __int_as_float(m1.y);
        acc[0] += fmaf(e0, p0.x, q0.x) + fmaf(e1, p1.x, q1.x);
        acc[1] += fmaf(e0, p0.y, q0.y) + fmaf(e1, p1.y, q1.y);
        acc[2] += fmaf(e0, p0.z, q0.z) + fmaf(e1, p1.z, q1.z);
        acc[3] += fmaf(e0, p0.w, q0.w) + fmaf(e1, p1.w, q1.w);
    }
    if (k < end) {
        int2 m0 = __ldg(meta + k);
        const float4* pq0 = reinterpret_cast<const float4*>(PQ3 + (size_t)m0.x * 8);
        float4 p0 = __ldg(pq0);
        float4 q0 = __ldg(pq0 + 1);
        float e0 = __int_as_float(m0.y);
        acc[0] += fmaf(e0, p0.x, q0.x);
        acc[1] += fmaf(e0, p0.y, q0.y);
        acc[2] += fmaf(e0, p0.z, q0.z);
        acc[3] += fmaf(e0, p0.w, q0.w);
    }

    float4 base = *reinterpret_cast<float4*>(OUT + (size_t)w * 4);
    float v0 = base.x + acc[0];
    float v1 = base.y + acc[1];
    float v2 = base.z + acc[2];
    float v3 = base.w + acc[3];

    float m = fmaxf(fmaxf(v0, v1), fmaxf(v2, v3));
    float s = __expf(v0 - m) + __expf(v1 - m) + __expf(v2 - m) + __expf(v3 - m);
    float lse = m + __logf(s);

    float4 o;
    o.x = v0 - lse; o.y = v1 - lse; o.z = v2 - lse; o.w = v3 - lse;
    *reinterpret_cast<float4*>(OUT + (size_t)w * 4) = o;
}

// =================================================================
extern "C" void kernel_launch(void* const* d_in, const int* in_sizes, int n_in,
                              void* d_out, int out_size)
{
    const float* x   = (const float*)d_in[0];
    const int*   ei  = (const int*)  d_in[1];
    const float* ea  = (const float*)d_in[2];
    const float* We1 = (const float*)d_in[3];
    const float* be1 = (const float*)d_in[4];
    const float* Wr1 = (const float*)d_in[5];
    const float* b1  = (const float*)d_in[6];
    const float* We2 = (const float*)d_in[7];
    const float* be2 = (const float*)d_in[8];
    const float* Wr2 = (const float*)d_in[9];
    const float* b2  = (const float*)d_in[10];
    const float* We3 = (const float*)d_in[11];
    const float* be3 = (const float*)d_in[12];
    const float* Wr3 = (const float*)d_in[13];
    const float* b3  = (const float*)d_in[14];

    const int N = in_sizes[0] / DIN;
    const int E = in_sizes[2];

    float *PQ3, *OUT = (float*)d_out;
    __half *XEh, *X1h, *Xh, *HAh, *HBh, *Wh;
    int *counts, *off, *cursor, *bsum, *boff;
    int2 *meta;
    cudaGetSymbolAddress((void**)&XEh, g_XEh);
    cudaGetSymbolAddress((void**)&X1h, g_X1h);
    cudaGetSymbolAddress((void**)&Xh, g_Xh);
    cudaGetSymbolAddress((void**)&HAh, g_HAh);
    cudaGetSymbolAddress((void**)&HBh, g_HBh);
    cudaGetSymbolAddress((void**)&PQ3, g_PQ3);
    cudaGetSymbolAddress((void**)&Wh, g_Wh);
    cudaGetSymbolAddress((void**)&counts, g_counts);
    cudaGetSymbolAddress((void**)&off, g_off);
    cudaGetSymbolAddress((void**)&cursor, g_cursor);
    cudaGetSymbolAddress((void**)&bsum, g_bsum);
    cudaGetSymbolAddress((void**)&boff, g_boff);
    cudaGetSymbolAddress((void**)&meta, g_meta);

    const int edge4Grid = (E / 4 + 256) / 256;
    const int rowGrid   = (N + 255) / 256;
    const int aggGrid   = (N * 32 + 255) / 256;
    const int tcGrid    = (N + 127) / 128;
    const int scanGrid  = (N + 2047) / 2048;
    const int cvtGrid   = (N * 64 / 8 + 255) / 256;

    // ---- CSR build + weight pre-transpose (layers 1-2) + x->fp16 ----
    zero_kernel<<<rowGrid, 256>>>(counts, N);
    hist_kernel<<<edge4Grid, 256>>>(ei, counts, E);
    scanA_kernel<<<scanGrid, 256>>>(counts, bsum, N);
    scanB_kernel<<<1, 64>>>(bsum, boff, off, scanGrid, N);
    scanC_kernel<<<scanGrid, 256>>>(counts, boff, off, cursor, N);
    scatter_kernel<<<edge4Grid, 256>>>(ei, ea, cursor, meta, E);
    pretrans_h_kernel<<<96, 256>>>(We1, be1, Wr1, We2, be2, Wr2, Wh);
    cvt_half_kernel<<<cvtGrid, 256>>>(x, Xh, N * 64);

    // ---- layer 1 ----
    aggx_h_kernel<<<aggGrid, 256>>>(off, meta, Xh, XEh, X1h, N);
    gemm192_f16<<<tcGrid, 256, F16_SMEM_BYTES>>>(XEh, X1h, Xh, Wh, b1, HAh, N);

    // ---- layer 2 ----
    aggx_h_kernel<<<aggGrid, 256>>>(off, meta, HAh, XEh, X1h, N);
    gemm192_f16<<<tcGrid, 256, F16_SMEM_BYTES>>>(XEh, X1h, HAh,
                                                 Wh + (size_t)3 * SWH, b2, HBh, N);

    // ---- layer 3: project-first (64->4), then 32B/edge aggregate ----
    gemm3_pq<<<rowGrid, 256>>>(HBh, We3, be3, Wr3, b3, PQ3, OUT, N);
    agg3_ls<<<rowGrid, 256>>>(off, meta, PQ3, OUT, N);
}